// round 6
// baseline (speedup 1.0000x reference)
#include <cuda_runtime.h>
#include <cuda_fp16.h>
#include <cstdint>
#include <cstddef>

#define N_NODES 4096
#define N_EDGES 16384
#define NODE_DIM 128
#define HIDDEN 128
#define EDGE_DIM 64
#define HEADS 4
#define OUT_DIM 64
#define CATDIM (HEADS * EDGE_DIM) /* 256 */
#define NB 288                    /* B rows: 256 P + 4 q + 28 zero pad */
#define NWX 320                   /* Wext padded cols */

// ---------------- scratch (static device globals; no allocation) ----------------
__device__ __align__(16) float g_Wext[NODE_DIM * NWX];                // 160 KB [d][c]
__device__ __align__(16) float g_bext[NWX];
__device__ __align__(16) __half g_Bhi[(size_t)NB * N_NODES];          // 2.4 MB [c][n]
__device__ __align__(16) __half g_Blo[(size_t)NB * N_NODES];
__device__ __align__(16) float g_Mu[(size_t)N_EDGES * CATDIM];        // 16.8 MB [e][c]
__device__ __align__(16) float g_score[HEADS * N_EDGES];
__device__ __align__(16) float g_coeff[HEADS * N_EDGES];
__device__ __align__(16) float g_U[(size_t)N_EDGES * CATDIM];         // 16.8 MB
__device__ unsigned g_mn_bits[CATDIM];
__device__ unsigned g_mx_bits[CATDIM];

// ---------------- helpers ----------------
__device__ __forceinline__ uint32_t smem_u32(const void* p) {
    uint32_t a;
    asm("{ .reg .u64 t; cvta.to.shared.u64 t, %1; cvt.u32.u64 %0, t; }" : "=r"(a) : "l"(p));
    return a;
}
__device__ __forceinline__ void cp16(uint32_t dst, const void* src) {
    asm volatile("cp.async.cg.shared.global [%0], [%1], 16;" :: "r"(dst), "l"(src));
}
__device__ __forceinline__ void ldmat4t(uint32_t (&r)[4], uint32_t addr) {
    asm volatile("ldmatrix.sync.aligned.m8n8.x4.trans.shared.b16 {%0,%1,%2,%3}, [%4];"
                 : "=r"(r[0]), "=r"(r[1]), "=r"(r[2]), "=r"(r[3]) : "r"(addr));
}
__device__ __forceinline__ void ldmat4(uint32_t (&r)[4], uint32_t addr) {
    asm volatile("ldmatrix.sync.aligned.m8n8.x4.shared.b16 {%0,%1,%2,%3}, [%4];"
                 : "=r"(r[0]), "=r"(r[1]), "=r"(r[2]), "=r"(r[3]) : "r"(addr));
}
__device__ __forceinline__ void hmma(float (&d)[4], const uint32_t (&a)[4],
                                     uint32_t b0, uint32_t b1) {
    asm volatile("mma.sync.aligned.m16n8k16.row.col.f32.f16.f16.f32 "
                 "{%0,%1,%2,%3}, {%4,%5,%6,%7}, {%8,%9}, {%0,%1,%2,%3};"
                 : "+f"(d[0]), "+f"(d[1]), "+f"(d[2]), "+f"(d[3])
                 : "r"(a[0]), "r"(a[1]), "r"(a[2]), "r"(a[3]), "r"(b0), "r"(b1));
}
__device__ __forceinline__ unsigned f2ord(float f) {
    unsigned u = __float_as_uint(f);
    return (u & 0x80000000u) ? ~u : (u | 0x80000000u);
}
__device__ __forceinline__ float ord2f(unsigned o) {
    unsigned u = (o & 0x80000000u) ? (o & 0x7FFFFFFFu) : ~o;
    return __uint_as_float(u);
}

// ---------------- k0: init minmax ----------------
__global__ void k0_init() {
    int t = threadIdx.x;
    if (t < CATDIM) { g_mn_bits[t] = 0xFFFFFFFFu; g_mx_bits[t] = 0u; }
}

// ---------------- kw: Wext[d][c] = (W1@W2 | W1@Wa | 0), bext ----------------
__global__ __launch_bounds__(128) void kw(const float* __restrict__ W1,
                                          const float* __restrict__ W2,
                                          const float* __restrict__ Wa,
                                          const float* __restrict__ b1)
{
    const int c = blockIdx.x;
    const int d = threadIdx.x;
    float v = 0.f;
    if (c < CATDIM) {
        const int h = c >> 6, o = c & 63;
        const float* w1 = &W1[h * NODE_DIM * HIDDEN + d * HIDDEN];
        const float* w2 = &W2[h * HIDDEN * EDGE_DIM + o];
#pragma unroll 4
        for (int k = 0; k < HIDDEN; ++k) v += w1[k] * w2[k * EDGE_DIM];
    } else if (c < CATDIM + HEADS) {
        const int h = c - CATDIM;
        const float* w1 = &W1[h * NODE_DIM * HIDDEN + d * HIDDEN];
        const float* wa = &Wa[h * HIDDEN];
#pragma unroll 4
        for (int k = 0; k < HIDDEN; ++k) v += w1[k] * wa[k];
    }
    g_Wext[d * NWX + c] = v;
    if (d == 0) {
        float b = 0.f;
        if (c < CATDIM) {
            const int h = c >> 6, o = c & 63;
            for (int k = 0; k < HIDDEN; ++k)
                b += b1[h * HIDDEN + k] * W2[h * HIDDEN * EDGE_DIM + k * EDGE_DIM + o];
        } else if (c < CATDIM + HEADS) {
            const int h = c - CATDIM;
            for (int k = 0; k < HIDDEN; ++k)
                b += b1[h * HIDDEN + k] * Wa[h * HIDDEN + k];
        }
        g_bext[c] = b;
    }
}

// ---------------- kP: [P|q][n][c] = node @ Wext + bext, write split-fp16 transposed [c][n] ----------------
__global__ __launch_bounds__(256) void kP(const float* __restrict__ node)
{
    __shared__ float As[16][64];
    __shared__ float Bs[16][64];
    __shared__ float sOut[64][65]; // [c][n]
    const int t = threadIdx.x;
    const int n0 = blockIdx.x * 64;
    const int c0 = blockIdx.y * 64;
    const int ty = t >> 4, tx = t & 15;
    float acc[4][4];
#pragma unroll
    for (int i = 0; i < 4; ++i)
#pragma unroll
        for (int j = 0; j < 4; ++j) acc[i][j] = 0.f;

    for (int d0 = 0; d0 < NODE_DIM; d0 += 16) {
        {
            int n = t >> 2, dq = (t & 3) * 4;
            float4 v = *(const float4*)&node[(n0 + n) * NODE_DIM + d0 + dq];
            As[dq + 0][n] = v.x; As[dq + 1][n] = v.y;
            As[dq + 2][n] = v.z; As[dq + 3][n] = v.w;
        }
        {
            int d = t >> 4, cq = (t & 15) * 4;
            *(float4*)&Bs[d][cq] = *(const float4*)&g_Wext[(d0 + d) * NWX + c0 + cq];
        }
        __syncthreads();
#pragma unroll
        for (int dd = 0; dd < 16; ++dd) {
            float a[4], b[4];
#pragma unroll
            for (int i = 0; i < 4; ++i) a[i] = As[dd][ty * 4 + i];
#pragma unroll
            for (int j = 0; j < 4; ++j) b[j] = Bs[dd][tx * 4 + j];
#pragma unroll
            for (int i = 0; i < 4; ++i)
#pragma unroll
                for (int j = 0; j < 4; ++j) acc[i][j] += a[i] * b[j];
        }
        __syncthreads();
    }
#pragma unroll
    for (int i = 0; i < 4; ++i)
#pragma unroll
        for (int j = 0; j < 4; ++j)
            sOut[tx * 4 + j][ty * 4 + i] = acc[i][j] + g_bext[c0 + tx * 4 + j];
    __syncthreads();
#pragma unroll
    for (int i = t; i < 2048; i += 256) {
        int cl = i >> 5, n2 = (i & 31) * 2;
        int c = c0 + cl;
        if (c >= NB) break;
        float v0 = sOut[cl][n2], v1 = sOut[cl][n2 + 1];
        __half h0 = __float2half_rn(v0), h1 = __float2half_rn(v1);
        __half l0 = __float2half_rn(v0 - __half2float(h0));
        __half l1 = __float2half_rn(v1 - __half2float(h1));
        size_t idx = (size_t)c * N_NODES + n0 + n2;
        *(__half2*)&g_Bhi[idx] = __halves2half2(h0, h1);
        *(__half2*)&g_Blo[idx] = __halves2half2(l0, l1);
    }
}

// ---------------- k2: HMMA split-fp16 GEMM  Mu[e, c] = incT @ [P|q] ----------------
// CTA: 64 e x 288 cols, grid 256, 2 CTAs/SM.
// A stage: 32 k-rows x [hi 128B | lo 128B | pad 16B] = 272B -> 8704B
// B stage: 288 c-rows x [hi 64B | lo 64B | pad 16B] = 144B -> 41472B
#define K2_OFF_B 8704
#define K2_SS 50176
#define K2_SMEM (2 * K2_SS)
#define NCHUNK (N_NODES / 32)

__global__ __launch_bounds__(256, 2) void k2_mma(const float* __restrict__ inc,
                                                 const float* __restrict__ ba)
{
    extern __shared__ char sm[];
    const int t = threadIdx.x;
    const int lane = t & 31, wid = t >> 5;
    const int e0 = blockIdx.x * 64;
    const int wm0 = (wid >> 2) * 32;   // 2 warps in m
    const int wn0 = (wid & 3) * 72;    // 4 warps in n (9 mma-n tiles each)
    const uint32_t sb = smem_u32(sm);

    float4 rA[2];
    auto ldgA = [&](int kt) {
#pragma unroll
        for (int it = 0; it < 2; ++it) {
            int idx = t + it * 256;
            int r = idx >> 4, f = idx & 15;
            rA[it] = *(const float4*)&inc[(size_t)(kt * 32 + r) * N_EDGES + e0 + f * 4];
        }
    };
    auto stsA = [&](int s) {
        char* ab = sm + s * K2_SS;
#pragma unroll
        for (int it = 0; it < 2; ++it) {
            int idx = t + it * 256;
            int r = idx >> 4, f = idx & 15;
            float4 v = rA[it];
            __half hx = __float2half_rn(v.x), hy = __float2half_rn(v.y);
            __half hz = __float2half_rn(v.z), hw = __float2half_rn(v.w);
            __half lx = __float2half_rn(v.x - __half2float(hx));
            __half ly = __float2half_rn(v.y - __half2float(hy));
            __half lz = __float2half_rn(v.z - __half2float(hz));
            __half lw = __float2half_rn(v.w - __half2float(hw));
            uint32_t off = r * 272 + f * 8;
            *(__half2*)(ab + off)       = __halves2half2(hx, hy);
            *(__half2*)(ab + off + 4)   = __halves2half2(hz, hw);
            *(__half2*)(ab + off + 128) = __halves2half2(lx, ly);
            *(__half2*)(ab + off + 132) = __halves2half2(lz, lw);
        }
    };
    auto cpB = [&](int s, int kt) {
        uint32_t bb = sb + s * K2_SS + K2_OFF_B;
#pragma unroll
        for (int i = t; i < NB * 8; i += 256) {
            int r = i >> 3, jj = i & 7;
            int hl = jj >> 2, j = jj & 3;
            const char* src = hl ? (const char*)g_Blo : (const char*)g_Bhi;
            size_t g = ((size_t)r * N_NODES + kt * 32) * 2 + j * 16;
            cp16(bb + r * 144 + hl * 64 + j * 16, src + g);
        }
        asm volatile("cp.async.commit_group;" ::: "memory");
    };

    float acc[2][9][4];
#pragma unroll
    for (int mt = 0; mt < 2; ++mt)
#pragma unroll
        for (int nt = 0; nt < 9; ++nt)
#pragma unroll
            for (int j = 0; j < 4; ++j) acc[mt][nt][j] = 0.f;

    // prologue
    ldgA(0);
    cpB(0, 0);
    stsA(0);
    ldgA(1);

    const int grp = lane >> 3, gi = lane & 7;
    const uint32_t bRow = (wn0 + (lane & 7)) * 144 + (grp >> 1) * 64 + (grp & 1) * 16;
    for (int kt = 0; kt < NCHUNK; ++kt) {
        const int buf = kt & 1;
        __syncthreads();
        if (kt + 1 < NCHUNK) {
            cpB(buf ^ 1, kt + 1);
            stsA(buf ^ 1);
            if (kt + 2 < NCHUNK) ldgA(kt + 2);
            asm volatile("cp.async.wait_group 1;" ::: "memory");
        } else {
            asm volatile("cp.async.wait_group 0;" ::: "memory");
        }
        __syncthreads();

        const uint32_t aBase = sb + buf * K2_SS;
        const uint32_t bBase = aBase + K2_OFF_B;
#pragma unroll
        for (int kk = 0; kk < 32; kk += 16) {
            uint32_t aH[2][4], aL[2][4];
            const int krow = kk + ((grp & 2) ? 8 : 0) + gi;
#pragma unroll
            for (int mt = 0; mt < 2; ++mt) {
                const uint32_t mcol = wm0 + mt * 16 + ((grp & 1) ? 8 : 0);
                ldmat4t(aH[mt], aBase + krow * 272 + mcol * 2);
                ldmat4t(aL[mt], aBase + krow * 272 + 128 + mcol * 2);
            }
            const uint32_t bK = bBase + bRow + kk * 2;
#pragma unroll
            for (int nt = 0; nt < 9; ++nt) {
                uint32_t b[4];  // hi-b0, hi-b1, lo-b0, lo-b1
                ldmat4(b, bK + nt * (8 * 144));
#pragma unroll
                for (int mt = 0; mt < 2; ++mt) {
                    hmma(acc[mt][nt], aH[mt], b[0], b[1]);
                    hmma(acc[mt][nt], aH[mt], b[2], b[3]);
                    hmma(acc[mt][nt], aL[mt], b[0], b[1]);
                }
            }
        }
    }

    // epilogue
#pragma unroll
    for (int mt = 0; mt < 2; ++mt) {
        const int e = e0 + wm0 + mt * 16 + (lane >> 2);
#pragma unroll
        for (int nt = 0; nt < 9; ++nt) {
            const int c = wn0 + nt * 8 + (lane & 3) * 2;
            if (c < CATDIM) {
                *(float2*)&g_Mu[(size_t)e * CATDIM + c] =
                    make_float2(acc[mt][nt][0], acc[mt][nt][1]);
                *(float2*)&g_Mu[(size_t)(e + 8) * CATDIM + c] =
                    make_float2(acc[mt][nt][2], acc[mt][nt][3]);
            } else if (c < CATDIM + HEADS) {
                const int h0 = c - CATDIM;
                float b0 = ba[h0], b1 = ba[h0 + 1];
                float s0 = acc[mt][nt][0] + b0, s1 = acc[mt][nt][1] + b1;
                float s2 = acc[mt][nt][2] + b0, s3 = acc[mt][nt][3] + b1;
                s0 = s0 > 0.f ? s0 : 0.2f * s0;
                s1 = s1 > 0.f ? s1 : 0.2f * s1;
                s2 = s2 > 0.f ? s2 : 0.2f * s2;
                s3 = s3 > 0.f ? s3 : 0.2f * s3;
                g_score[h0 * N_EDGES + e] = s0;
                g_score[(h0 + 1) * N_EDGES + e] = s1;
                g_score[h0 * N_EDGES + e + 8] = s2;
                g_score[(h0 + 1) * N_EDGES + e + 8] = s3;
            }
        }
    }
}

// ---------------- k4: softmax over edges, per head ----------------
__global__ void k4_softmax()
{
    __shared__ float red[1024];
    const int h = blockIdx.x;
    const int t = threadIdx.x;
    const float* srow = &g_score[h * N_EDGES];

    float m = -3.4e38f;
    for (int i = t; i < N_EDGES; i += 1024) m = fmaxf(m, srow[i]);
    red[t] = m;
    __syncthreads();
    for (int s = 512; s > 0; s >>= 1) {
        if (t < s) red[t] = fmaxf(red[t], red[t + s]);
        __syncthreads();
    }
    m = red[0];
    __syncthreads();

    float sum = 0.f;
    for (int i = t; i < N_EDGES; i += 1024) sum += expf(srow[i] - m);
    red[t] = sum;
    __syncthreads();
    for (int s = 512; s > 0; s >>= 1) {
        if (t < s) red[t] += red[t + s];
        __syncthreads();
    }
    float inv = 1.0f / red[0];

    for (int i = t; i < N_EDGES; i += 1024)
        g_coeff[h * N_EDGES + i] = expf(srow[i] - m) * inv;
}

// ---------------- k5: u = coeff*Mu + b2 ; column min/max ----------------
__global__ __launch_bounds__(256) void k5_u(const float* __restrict__ b2)
{
    const int c = threadIdx.x;
    const int e0 = blockIdx.x * 64;
    const int h = c >> 6;
    const float bb = b2[c];
    float mn = 3.4e38f, mx = -3.4e38f;
    for (int i = 0; i < 64; ++i) {
        int e = e0 + i;
        float u = g_coeff[h * N_EDGES + e] * g_Mu[(size_t)e * CATDIM + c] + bb;
        g_U[(size_t)e * CATDIM + c] = u;
        mn = fminf(mn, u); mx = fmaxf(mx, u);
    }
    atomicMin(&g_mn_bits[c], f2ord(mn));
    atomicMax(&g_mx_bits[c], f2ord(mx));
}

// ---------------- k6: out = relu(minmax_norm(U)) @ Wout + bout ----------------
__global__ __launch_bounds__(256) void k6_out(const float* __restrict__ Wout,
                                              const float* __restrict__ bout,
                                              float* __restrict__ out)
{
    __shared__ float sX[32 * CATDIM];
    __shared__ float sMin[CATDIM];
    __shared__ float sInv[CATDIM];
    const int t = threadIdx.x;
    const int e0 = blockIdx.x * 32;

    for (int i = t; i < CATDIM; i += 256) {
        float mn = ord2f(g_mn_bits[i]);
        float mx = ord2f(g_mx_bits[i]);
        sMin[i] = mn;
        sInv[i] = 1.0f / (mx - mn + 1e-8f);
    }
    __syncthreads();
    for (int i = t; i < 32 * CATDIM / 4; i += 256) {
        int l = i * 4; int e = l >> 8; int c = l & 255;
        float4 v = *(const float4*)&g_U[(size_t)(e0 + e) * CATDIM + c];
        v.x = fmaxf((v.x - sMin[c + 0]) * sInv[c + 0], 0.f);
        v.y = fmaxf((v.y - sMin[c + 1]) * sInv[c + 1], 0.f);
        v.z = fmaxf((v.z - sMin[c + 2]) * sInv[c + 2], 0.f);
        v.w = fmaxf((v.w - sMin[c + 3]) * sInv[c + 3], 0.f);
        *(float4*)&sX[l] = v;
    }
    __syncthreads();

    const int ty = t >> 4, tx = t & 15;
    float acc[2][4] = {{0.f,0.f,0.f,0.f},{0.f,0.f,0.f,0.f}};
#pragma unroll 4
    for (int c = 0; c < CATDIM; ++c) {
        float4 w = *(const float4*)&Wout[c * OUT_DIM + tx * 4];
#pragma unroll
        for (int ee = 0; ee < 2; ++ee) {
            float xv = sX[(ty + ee * 16) * CATDIM + c];
            acc[ee][0] += xv * w.x; acc[ee][1] += xv * w.y;
            acc[ee][2] += xv * w.z; acc[ee][3] += xv * w.w;
        }
    }
    float4 bo = *(const float4*)&bout[tx * 4];
#pragma unroll
    for (int ee = 0; ee < 2; ++ee) {
        int e = e0 + ty + ee * 16;
        out[(size_t)e * OUT_DIM + tx * 4 + 0] = acc[ee][0] + bo.x;
        out[(size_t)e * OUT_DIM + tx * 4 + 1] = acc[ee][1] + bo.y;
        out[(size_t)e * OUT_DIM + tx * 4 + 2] = acc[ee][2] + bo.z;
        out[(size_t)e * OUT_DIM + tx * 4 + 3] = acc[ee][3] + bo.w;
    }
}

// ---------------- launch ----------------
extern "C" void kernel_launch(void* const* d_in, const int* in_sizes, int n_in,
                              void* d_out, int out_size)
{
    (void)in_sizes; (void)n_in; (void)out_size;
    const float* node = (const float*)d_in[0];
    const float* inc  = (const float*)d_in[1];
    const float* W1   = (const float*)d_in[2];
    const float* b1   = (const float*)d_in[3];
    const float* Wa   = (const float*)d_in[4];
    const float* ba   = (const float*)d_in[5];
    const float* W2   = (const float*)d_in[6];
    const float* b2   = (const float*)d_in[7];
    const float* Wout = (const float*)d_in[8];
    const float* bout = (const float*)d_in[9];
    float* out = (float*)d_out;

    cudaFuncSetAttribute(k2_mma, cudaFuncAttributeMaxDynamicSharedMemorySize, K2_SMEM);

    k0_init<<<1, 256>>>();
    kw<<<NWX, 128>>>(W1, W2, Wa, b1);
    kP<<<dim3(N_NODES / 64, NWX / 64), 256>>>(node);
    k2_mma<<<N_EDGES / 64, 256, K2_SMEM>>>(inc, ba);
    k4_softmax<<<HEADS, 1024>>>();
    k5_u<<<N_EDGES / 64, 256>>>(b2);
    k6_out<<<N_EDGES / 32, 256>>>(Wout, bout, out);
}

// round 7
// speedup vs baseline: 1.4585x; 1.4585x over previous
#include <cuda_runtime.h>
#include <cuda_fp16.h>
#include <cstdint>
#include <cstddef>

#define N_NODES 4096
#define N_EDGES 16384
#define NODE_DIM 128
#define HIDDEN 128
#define EDGE_DIM 64
#define HEADS 4
#define OUT_DIM 64
#define TCOLS (HEADS * HIDDEN)    /* 512 */
#define CATDIM (HEADS * EDGE_DIM) /* 256 */
#define NB 288                    /* B rows: 256 P + 4 q + 28 zero pad */
#define KCH 32                    /* k per chunk */
#define NCHUNK (N_NODES / KCH)    /* 128 */
#define BCHUNK (NB * 128)         /* bytes per B chunk: 288 rows x (64 hi + 64 lo) = 36864 */

// ---------------- scratch (static device globals; no allocation) ----------------
__device__ __align__(16) float g_t[(size_t)N_NODES * TCOLS];          // 8 MB
// blocked split-fp16 B: [chunk][seg 0..7][c 0..287][16B]; seg 0-3 = hi k-groups, 4-7 = lo
__device__ __align__(16) char g_Bk[(size_t)NCHUNK * BCHUNK];          // 4.7 MB
__device__ __align__(16) float g_Mu[(size_t)N_EDGES * CATDIM];        // 16.8 MB
__device__ __align__(16) float g_score[HEADS * N_EDGES];
__device__ __align__(16) float g_coeff[HEADS * N_EDGES];
__device__ __align__(16) float g_U[(size_t)N_EDGES * CATDIM];         // 16.8 MB
__device__ unsigned g_mn_bits[CATDIM];
__device__ unsigned g_mx_bits[CATDIM];

// ---------------- helpers ----------------
__device__ __forceinline__ uint32_t smem_u32(const void* p) {
    uint32_t a;
    asm("{ .reg .u64 t; cvta.to.shared.u64 t, %1; cvt.u32.u64 %0, t; }" : "=r"(a) : "l"(p));
    return a;
}
__device__ __forceinline__ void ldmat4t(uint32_t (&r)[4], uint32_t addr) {
    asm volatile("ldmatrix.sync.aligned.m8n8.x4.trans.shared.b16 {%0,%1,%2,%3}, [%4];"
                 : "=r"(r[0]), "=r"(r[1]), "=r"(r[2]), "=r"(r[3]) : "r"(addr));
}
__device__ __forceinline__ void ldmat4(uint32_t (&r)[4], uint32_t addr) {
    asm volatile("ldmatrix.sync.aligned.m8n8.x4.shared.b16 {%0,%1,%2,%3}, [%4];"
                 : "=r"(r[0]), "=r"(r[1]), "=r"(r[2]), "=r"(r[3]) : "r"(addr));
}
__device__ __forceinline__ void hmma(float (&d)[4], const uint32_t (&a)[4],
                                     uint32_t b0, uint32_t b1) {
    asm volatile("mma.sync.aligned.m16n8k16.row.col.f32.f16.f16.f32 "
                 "{%0,%1,%2,%3}, {%4,%5,%6,%7}, {%8,%9}, {%0,%1,%2,%3};"
                 : "+f"(d[0]), "+f"(d[1]), "+f"(d[2]), "+f"(d[3])
                 : "r"(a[0]), "r"(a[1]), "r"(a[2]), "r"(a[3]), "r"(b0), "r"(b1));
}
#define MBAR_INIT(a, c) asm volatile("mbarrier.init.shared.b64 [%0], %1;" :: "r"(a), "r"(c) : "memory")
#define MBAR_EXPECT_TX(a, n) \
    asm volatile("mbarrier.arrive.expect_tx.shared.b64 _, [%0], %1;" :: "r"(a), "r"(n) : "memory")
#define MBAR_WAIT(a, ph) do {                                                                  \
    uint32_t _m = (a), _p = (ph), _d;                                                          \
    asm volatile("{\n\t.reg .pred p;\n\t"                                                      \
        "mbarrier.try_wait.parity.acquire.cta.shared::cta.b64 p, [%1], %2;\n\t"                \
        "selp.b32 %0, 1, 0, p;\n\t}" : "=r"(_d) : "r"(_m), "r"(_p) : "memory");                \
    if (!_d) {                                                                                 \
        asm volatile("{\n\t.reg .pred P1;\n\tWL%=: \n\t"                                       \
            "mbarrier.try_wait.parity.acquire.cta.shared::cta.b64 P1, [%0], %1, 0x989680;\n\t" \
            "@P1 bra.uni WD%=;\n\tbra.uni WL%=;\n\tWD%=:\n\t}"                                 \
            :: "r"(_m), "r"(_p) : "memory");                                                   \
    } } while (0)
__device__ __forceinline__ void bulk_ld(uint32_t dst, const void* src, uint32_t bytes,
                                        uint32_t mbar) {
    asm volatile("cp.async.bulk.shared::cta.global.mbarrier::complete_tx::bytes "
                 "[%0], [%1], %2, [%3];"
                 :: "r"(dst), "l"(src), "r"(bytes), "r"(mbar) : "memory");
}
__device__ __forceinline__ unsigned f2ord(float f) {
    unsigned u = __float_as_uint(f);
    return (u & 0x80000000u) ? ~u : (u | 0x80000000u);
}
__device__ __forceinline__ float ord2f(unsigned o) {
    unsigned u = (o & 0x80000000u) ? (o & 0x7FFFFFFFu) : ~o;
    return __uint_as_float(u);
}

// ---------------- k0: init minmax + zero the 28 pad rows of every B chunk ----------------
__global__ void k0_init() {
    int idx = blockIdx.x * blockDim.x + threadIdx.x;
    if (idx < CATDIM) { g_mn_bits[idx] = 0xFFFFFFFFu; g_mx_bits[idx] = 0u; }
    const int total = NCHUNK * 8 * 28;  // 16B units
    for (int id = idx; id < total; id += gridDim.x * blockDim.x) {
        int chunk = id / 224;
        int r = id % 224;
        int s = r / 28;
        int c = 260 + r % 28;
        *(uint4*)&g_Bk[(size_t)chunk * BCHUNK + ((size_t)s * NB + c) * 16] =
            make_uint4(0, 0, 0, 0);
    }
}

// ---------------- k1: t[n, h*128+k] = node @ W1[h] + b1[h] (fp32) ----------------
__global__ __launch_bounds__(256) void k1_node_transform(
    const float* __restrict__ node, const float* __restrict__ W1,
    const float* __restrict__ b1)
{
    __shared__ float As[16][64];
    __shared__ float Bs[16][64];
    const int t = threadIdx.x;
    const int n0 = blockIdx.x * 64;
    const int c0 = blockIdx.y * 64;
    const int h = c0 >> 7;
    const int k0 = c0 & 127;
    const int ty = t >> 4, tx = t & 15;
    float acc[4][4];
#pragma unroll
    for (int i = 0; i < 4; ++i)
#pragma unroll
        for (int j = 0; j < 4; ++j) acc[i][j] = 0.f;

    for (int d0 = 0; d0 < NODE_DIM; d0 += 16) {
        {
            int n = t >> 2, dq = (t & 3) * 4;
            float4 v = *(const float4*)&node[(n0 + n) * NODE_DIM + d0 + dq];
            As[dq + 0][n] = v.x; As[dq + 1][n] = v.y;
            As[dq + 2][n] = v.z; As[dq + 3][n] = v.w;
        }
        {
            int d = t >> 4, cq = (t & 15) * 4;
            *(float4*)&Bs[d][cq] =
                *(const float4*)&W1[h * (NODE_DIM * HIDDEN) + (d0 + d) * HIDDEN + k0 + cq];
        }
        __syncthreads();
#pragma unroll
        for (int dd = 0; dd < 16; ++dd) {
            float a[4], b[4];
#pragma unroll
            for (int i = 0; i < 4; ++i) a[i] = As[dd][ty * 4 + i];
#pragma unroll
            for (int j = 0; j < 4; ++j) b[j] = Bs[dd][tx * 4 + j];
#pragma unroll
            for (int i = 0; i < 4; ++i)
#pragma unroll
                for (int j = 0; j < 4; ++j) acc[i][j] += a[i] * b[j];
        }
        __syncthreads();
    }
#pragma unroll
    for (int i = 0; i < 4; ++i)
#pragma unroll
        for (int j = 0; j < 4; ++j)
            g_t[(size_t)(n0 + ty * 4 + i) * TCOLS + c0 + tx * 4 + j] =
                acc[i][j] + b1[h * HIDDEN + k0 + tx * 4 + j];
}

// ---------------- write one split-fp16 value pair into the blocked B layout ----------------
__device__ __forceinline__ void bk_store_pair(int c, int n, float v0, float v1) {
    // n even; n, n+1 in same 16B seg
    __half h0 = __float2half_rn(v0), h1 = __float2half_rn(v1);
    __half l0 = __float2half_rn(v0 - __half2float(h0));
    __half l1 = __float2half_rn(v1 - __half2float(h1));
    int chunk = n >> 5, nin = n & 31;
    size_t base = (size_t)chunk * BCHUNK + (((size_t)(nin >> 3)) * NB + c) * 16 + (nin & 7) * 2;
    *(__half2*)&g_Bk[base] = __halves2half2(h0, h1);
    *(__half2*)&g_Bk[base + 4 * NB * 16] = __halves2half2(l0, l1);
}

// ---------------- k1b: P = t@W2, q = t.Wa; write blocked split-fp16 ----------------
__global__ __launch_bounds__(256) void k1b_project(
    const float* __restrict__ W2, const float* __restrict__ Wa)
{
    extern __shared__ float smf[];
    float* sT = smf;                 // [64][132]
    float* sW2 = smf + 64 * 132;     // [128][68]
    float* sWa = sW2 + 128 * 68;     // [128]
    const int t = threadIdx.x;
    const int n0 = blockIdx.x * 64;
    const int h = blockIdx.y;

    for (int i = t; i < 64 * 32; i += 256) {
        int n = i >> 5, k4 = (i & 31) * 4;
        *(float4*)&sT[n * 132 + k4] =
            *(const float4*)&g_t[(size_t)(n0 + n) * TCOLS + h * HIDDEN + k4];
    }
    for (int i = t; i < 128 * 16; i += 256) {
        int k = i >> 4, o4 = (i & 15) * 4;
        *(float4*)&sW2[k * 68 + o4] =
            *(const float4*)&W2[(size_t)h * HIDDEN * EDGE_DIM + k * EDGE_DIM + o4];
    }
    if (t < 128) sWa[t] = Wa[h * HIDDEN + t];
    __syncthreads();

    const int ty = t >> 4, tx = t & 15;
    float acc[4][4] = {};
    for (int k = 0; k < HIDDEN; ++k) {
        float4 w = *(const float4*)&sW2[k * 68 + tx * 4];
#pragma unroll
        for (int i = 0; i < 4; ++i) {
            float a = sT[(ty * 4 + i) * 132 + k];
            acc[i][0] += a * w.x; acc[i][1] += a * w.y;
            acc[i][2] += a * w.z; acc[i][3] += a * w.w;
        }
    }
#pragma unroll
    for (int j = 0; j < 4; ++j) {
        int c = h * EDGE_DIM + tx * 4 + j;
        bk_store_pair(c, n0 + ty * 4 + 0, acc[0][j], acc[1][j]);
        bk_store_pair(c, n0 + ty * 4 + 2, acc[2][j], acc[3][j]);
    }
    if (tx == 0) {
        int c = CATDIM + h;
        float q[4];
#pragma unroll
        for (int i = 0; i < 4; ++i) {
            int n = ty * 4 + i;
            float s = 0.f;
            for (int k = 0; k < HIDDEN; ++k) s += sT[n * 132 + k] * sWa[k];
            q[i] = s;
        }
        bk_store_pair(c, n0 + ty * 4 + 0, q[0], q[1]);
        bk_store_pair(c, n0 + ty * 4 + 2, q[2], q[3]);
    }
}

// ---------------- k2: HMMA split-fp16 GEMM  Mu[e, c] = incT @ [P|q] ----------------
// CTA 128e x 288c, 512 threads (16 warps: 4m x 4n, warp tile 32x72), 2-stage.
// A stage: 32 k-rows x [hi 256B | lo 256B | pad 16B] = 528B -> 16896B
// B stage: one blocked chunk = 36864B (loaded with a single cp.async.bulk)
#define K2_ASZ 16896
#define K2_SS (K2_ASZ + BCHUNK)  /* 53760 */
#define K2_SMEM (2 * K2_SS)      /* 107520 */

__global__ __launch_bounds__(512) void k2_mma(const float* __restrict__ inc,
                                              const float* __restrict__ ba)
{
    extern __shared__ char sm[];
    __shared__ __align__(8) unsigned long long mbar[2];
    const int t = threadIdx.x;
    const int lane = t & 31, wid = t >> 5;
    const int e0 = blockIdx.x * 128;
    const int wm0 = (wid >> 2) * 32;   // 4 warps in m
    const int wn0 = (wid & 3) * 72;    // 4 warps in n (9 mma-n tiles each)
    const uint32_t sb = smem_u32(sm);

    if (t == 0) {
        MBAR_INIT(smem_u32(&mbar[0]), 1);
        MBAR_INIT(smem_u32(&mbar[1]), 1);
    }
    __syncthreads();

    float4 rA[2];
    auto ldgA = [&](int kt) {
#pragma unroll
        for (int it = 0; it < 2; ++it) {
            int idx = t + it * 512;
            int r = idx >> 5, f = idx & 31;
            rA[it] = *(const float4*)&inc[(size_t)(kt * KCH + r) * N_EDGES + e0 + f * 4];
        }
    };
    auto stsA = [&](int s) {
        char* ab = sm + s * K2_SS;
#pragma unroll
        for (int it = 0; it < 2; ++it) {
            int idx = t + it * 512;
            int r = idx >> 5, f = idx & 31;
            float4 v = rA[it];
            __half hx = __float2half_rn(v.x), hy = __float2half_rn(v.y);
            __half hz = __float2half_rn(v.z), hw = __float2half_rn(v.w);
            __half lx = __float2half_rn(v.x - __half2float(hx));
            __half ly = __float2half_rn(v.y - __half2float(hy));
            __half lz = __float2half_rn(v.z - __half2float(hz));
            __half lw = __float2half_rn(v.w - __half2float(hw));
            uint32_t off = r * 528 + f * 8;
            *(__half2*)(ab + off)       = __halves2half2(hx, hy);
            *(__half2*)(ab + off + 4)   = __halves2half2(hz, hw);
            *(__half2*)(ab + off + 256) = __halves2half2(lx, ly);
            *(__half2*)(ab + off + 260) = __halves2half2(lz, lw);
        }
    };
    auto loadB = [&](int s, int kt) {
        if (t == 0) {
            uint32_t mb = smem_u32(&mbar[s]);
            MBAR_EXPECT_TX(mb, (uint32_t)BCHUNK);
            bulk_ld(sb + s * K2_SS + K2_ASZ, g_Bk + (size_t)kt * BCHUNK, BCHUNK, mb);
        }
    };

    float acc[2][9][4];
#pragma unroll
    for (int mt = 0; mt < 2; ++mt)
#pragma unroll
        for (int nt = 0; nt < 9; ++nt)
#pragma unroll
            for (int j = 0; j < 4; ++j) acc[mt][nt][j] = 0.f;

    // prologue
    loadB(0, 0);
    loadB(1, 1);
    ldgA(0); stsA(0);
    ldgA(1); stsA(1);
    ldgA(2);

    const int grp = lane >> 3, gi = lane & 7;
    // B lane addressing: matrices grp0=hi k-sub0, grp1=hi k-sub1, grp2=lo k-sub0, grp3=lo k-sub1
    const uint32_t bLanePart = ((grp & 1) + ((grp >> 1) << 2)) * (NB * 16) +
                               (wn0 + (lane & 7)) * 16;
    int ph0 = 0, ph1 = 0;
    for (int kt = 0; kt < NCHUNK; ++kt) {
        const int buf = kt & 1;
        if (buf == 0) { MBAR_WAIT(smem_u32(&mbar[0]), ph0); ph0 ^= 1; }
        else          { MBAR_WAIT(smem_u32(&mbar[1]), ph1); ph1 ^= 1; }
        __syncthreads();

        const uint32_t aBase = sb + buf * K2_SS;
        const uint32_t bBase = aBase + K2_ASZ + bLanePart;
#pragma unroll
        for (int kk = 0; kk < KCH; kk += 16) {
            uint32_t aH[2][4], aL[2][4];
            const int krow = kk + ((grp & 2) ? 8 : 0) + gi;
#pragma unroll
            for (int mt = 0; mt < 2; ++mt) {
                const uint32_t mcol = wm0 + mt * 16 + ((grp & 1) ? 8 : 0);
                ldmat4t(aH[mt], aBase + krow * 528 + mcol * 2);
                ldmat4t(aL[mt], aBase + krow * 528 + 256 + mcol * 2);
            }
            const uint32_t bK = bBase + (kk >> 4) * (2 * NB * 16);
#pragma unroll
            for (int nt = 0; nt < 9; ++nt) {
                uint32_t b[4];  // hi-b0, hi-b1, lo-b0, lo-b1
                ldmat4(b, bK + nt * 128);
#pragma unroll
                for (int mt = 0; mt < 2; ++mt) {
                    hmma(acc[mt][nt], aH[mt], b[0], b[1]);
                    hmma(acc[mt][nt], aH[mt], b[2], b[3]);
                    hmma(acc[mt][nt], aL[mt], b[0], b[1]);
                }
            }
        }
        __syncthreads();
        if (kt + 2 < NCHUNK) {
            loadB(buf, kt + 2);
            stsA(buf);
            if (kt + 3 < NCHUNK) ldgA(kt + 3);
        }
    }

    // epilogue
#pragma unroll
    for (int mt = 0; mt < 2; ++mt) {
        const int e = e0 + wm0 + mt * 16 + (lane >> 2);
#pragma unroll
        for (int nt = 0; nt < 9; ++nt) {
            const int c = wn0 + nt * 8 + (lane & 3) * 2;
            if (c < CATDIM) {
                *(float2*)&g_Mu[(size_t)e * CATDIM + c] =
                    make_float2(acc[mt][nt][0], acc[mt][nt][1]);
                *(float2*)&g_Mu[(size_t)(e + 8) * CATDIM + c] =
                    make_float2(acc[mt][nt][2], acc[mt][nt][3]);
            } else if (c < CATDIM + HEADS) {
                const int h0 = c - CATDIM;
                float b0 = ba[h0], b1 = ba[h0 + 1];
                float s0 = acc[mt][nt][0] + b0, s1 = acc[mt][nt][1] + b1;
                float s2 = acc[mt][nt][2] + b0, s3 = acc[mt][nt][3] + b1;
                s0 = s0 > 0.f ? s0 : 0.2f * s0;
                s1 = s1 > 0.f ? s1 : 0.2f * s1;
                s2 = s2 > 0.f ? s2 : 0.2f * s2;
                s3 = s3 > 0.f ? s3 : 0.2f * s3;
                g_score[h0 * N_EDGES + e] = s0;
                g_score[(h0 + 1) * N_EDGES + e] = s1;
                g_score[h0 * N_EDGES + e + 8] = s2;
                g_score[(h0 + 1) * N_EDGES + e + 8] = s3;
            }
        }
    }
}

// ---------------- k4: softmax over edges, per head ----------------
__global__ void k4_softmax()
{
    __shared__ float red[1024];
    const int h = blockIdx.x;
    const int t = threadIdx.x;
    const float* srow = &g_score[h * N_EDGES];

    float m = -3.4e38f;
    for (int i = t; i < N_EDGES; i += 1024) m = fmaxf(m, srow[i]);
    red[t] = m;
    __syncthreads();
    for (int s = 512; s > 0; s >>= 1) {
        if (t < s) red[t] = fmaxf(red[t], red[t + s]);
        __syncthreads();
    }
    m = red[0];
    __syncthreads();

    float sum = 0.f;
    for (int i = t; i < N_EDGES; i += 1024) sum += expf(srow[i] - m);
    red[t] = sum;
    __syncthreads();
    for (int s = 512; s > 0; s >>= 1) {
        if (t < s) red[t] += red[t + s];
        __syncthreads();
    }
    float inv = 1.0f / red[0];

    for (int i = t; i < N_EDGES; i += 1024)
        g_coeff[h * N_EDGES + i] = expf(srow[i] - m) * inv;
}

// ---------------- k5: u = coeff*Mu + b2 ; column min/max ----------------
__global__ __launch_bounds__(256) void k5_u(const float* __restrict__ b2)
{
    const int c = threadIdx.x;
    const int e0 = blockIdx.x * 64;
    const int h = c >> 6;
    const float bb = b2[c];
    float mn = 3.4e38f, mx = -3.4e38f;
    for (int i = 0; i < 64; ++i) {
        int e = e0 + i;
        float u = g_coeff[h * N_EDGES + e] * g_Mu[(size_t)e * CATDIM + c] + bb;
        g_U[(size_t)e * CATDIM + c] = u;
        mn = fminf(mn, u); mx = fmaxf(mx, u);
    }
    atomicMin(&g_mn_bits[c], f2ord(mn));
    atomicMax(&g_mx_bits[c], f2ord(mx));
}

// ---------------- k6: out = relu(minmax_norm(U)) @ Wout + bout ----------------
__global__ __launch_bounds__(256) void k6_out(const float* __restrict__ Wout,
                                              const float* __restrict__ bout,
                                              float* __restrict__ out)
{
    __shared__ float sX[32 * CATDIM];
    __shared__ float sMin[CATDIM];
    __shared__ float sInv[CATDIM];
    const int t = threadIdx.x;
    const int e0 = blockIdx.x * 32;

    for (int i = t; i < CATDIM; i += 256) {
        float mn = ord2f(g_mn_bits[i]);
        float mx = ord2f(g_mx_bits[i]);
        sMin[i] = mn;
        sInv[i] = 1.0f / (mx - mn + 1e-8f);
    }
    __syncthreads();
    for (int i = t; i < 32 * CATDIM / 4; i += 256) {
        int l = i * 4; int e = l >> 8; int c = l & 255;
        float4 v = *(const float4*)&g_U[(size_t)(e0 + e) * CATDIM + c];
        v.x = fmaxf((v.x - sMin[c + 0]) * sInv[c + 0], 0.f);
        v.y = fmaxf((v.y - sMin[c + 1]) * sInv[c + 1], 0.f);
        v.z = fmaxf((v.z - sMin[c + 2]) * sInv[c + 2], 0.f);
        v.w = fmaxf((v.w - sMin[c + 3]) * sInv[c + 3], 0.f);
        *(float4*)&sX[l] = v;
    }
    __syncthreads();

    const int ty = t >> 4, tx = t & 15;
    float acc[2][4] = {{0.f,0.f,0.f,0.f},{0.f,0.f,0.f,0.f}};
#pragma unroll 4
    for (int c = 0; c < CATDIM; ++c) {
        float4 w = *(const float4*)&Wout[c * OUT_DIM + tx * 4];
#pragma unroll
        for (int ee = 0; ee < 2; ++ee) {
            float xv = sX[(ty + ee * 16) * CATDIM + c];
            acc[ee][0] += xv * w.x; acc[ee][1] += xv * w.y;
            acc[ee][2] += xv * w.z; acc[ee][3] += xv * w.w;
        }
    }
    float4 bo = *(const float4*)&bout[tx * 4];
#pragma unroll
    for (int ee = 0; ee < 2; ++ee) {
        int e = e0 + ty + ee * 16;
        out[(size_t)e * OUT_DIM + tx * 4 + 0] = acc[ee][0] + bo.x;
        out[(size_t)e * OUT_DIM + tx * 4 + 1] = acc[ee][1] + bo.y;
        out[(size_t)e * OUT_DIM + tx * 4 + 2] = acc[ee][2] + bo.z;
        out[(size_t)e * OUT_DIM + tx * 4 + 3] = acc[ee][3] + bo.w;
    }
}

// ---------------- launch ----------------
extern "C" void kernel_launch(void* const* d_in, const int* in_sizes, int n_in,
                              void* d_out, int out_size)
{
    (void)in_sizes; (void)n_in; (void)out_size;
    const float* node = (const float*)d_in[0];
    const float* inc  = (const float*)d_in[1];
    const float* W1   = (const float*)d_in[2];
    const float* b1   = (const float*)d_in[3];
    const float* Wa   = (const float*)d_in[4];
    const float* ba   = (const float*)d_in[5];
    const float* W2   = (const float*)d_in[6];
    const float* b2   = (const float*)d_in[7];
    const float* Wout = (const float*)d_in[8];
    const float* bout = (const float*)d_in[9];
    float* out = (float*)d_out;

    cudaFuncSetAttribute(k2_mma, cudaFuncAttributeMaxDynamicSharedMemorySize, K2_SMEM);
    cudaFuncSetAttribute(k1b_project, cudaFuncAttributeMaxDynamicSharedMemorySize, 69120);

    k0_init<<<64, 256>>>();
    k1_node_transform<<<dim3(N_NODES / 64, TCOLS / 64), 256>>>(node, W1, b1);
    k1b_project<<<dim3(N_NODES / 64, HEADS), 256, 69120>>>(W2, Wa);
    k2_mma<<<N_EDGES / 128, 512, K2_SMEM>>>(inc, ba);
    k4_softmax<<<HEADS, 1024>>>();
    k5_u<<<N_EDGES / 64, 256>>>(b2);
    k6_out<<<N_EDGES / 32, 256>>>(Wout, bout, out);
}

// round 12
// speedup vs baseline: 1.6327x; 1.1194x over previous
#include <cuda_runtime.h>
#include <cuda_fp16.h>
#include <cstdint>
#include <cstddef>

#define N_NODES 4096
#define N_EDGES 16384
#define NODE_DIM 128
#define HIDDEN 128
#define EDGE_DIM 64
#define HEADS 4
#define OUT_DIM 64
#define TCOLS (HEADS * HIDDEN)    /* 512 */
#define CATDIM (HEADS * EDGE_DIM) /* 256 */
#define NB 288                    /* B rows: 256 P + 4 q + 28 zero pad */
#define KCH 64                    /* k per chunk */
#define NCHUNK (N_NODES / KCH)    /* 64 */
#define BCHUNK (NB * 256)         /* bytes per B chunk: 288 rows x (128 hi + 128 lo) = 73728 */

// ---------------- scratch (static device globals; no allocation) ----------------
__device__ __align__(16) float g_t[(size_t)N_NODES * TCOLS];          // 8 MB
// blocked split-fp16 B: [chunk][seg 0..15][c 0..287][16B]; seg 0-7 = hi k-groups, 8-15 = lo
__device__ __align__(16) char g_Bk[(size_t)NCHUNK * BCHUNK];          // 4.7 MB
__device__ __align__(16) float g_Mu[(size_t)N_EDGES * CATDIM];        // 16.8 MB
__device__ __align__(16) float g_score[HEADS * N_EDGES];
__device__ __align__(16) float g_coeff[HEADS * N_EDGES];
__device__ __align__(16) float g_U[(size_t)N_EDGES * CATDIM];         // 16.8 MB
__device__ unsigned g_mn_bits[CATDIM];
__device__ unsigned g_mx_bits[CATDIM];

// ---------------- helpers ----------------
__device__ __forceinline__ uint32_t smem_u32(const void* p) {
    uint32_t a;
    asm("{ .reg .u64 t; cvta.to.shared.u64 t, %1; cvt.u32.u64 %0, t; }" : "=r"(a) : "l"(p));
    return a;
}
__device__ __forceinline__ void ldmat4t(uint32_t (&r)[4], uint32_t addr) {
    asm volatile("ldmatrix.sync.aligned.m8n8.x4.trans.shared.b16 {%0,%1,%2,%3}, [%4];"
                 : "=r"(r[0]), "=r"(r[1]), "=r"(r[2]), "=r"(r[3]) : "r"(addr));
}
__device__ __forceinline__ void ldmat4(uint32_t (&r)[4], uint32_t addr) {
    asm volatile("ldmatrix.sync.aligned.m8n8.x4.shared.b16 {%0,%1,%2,%3}, [%4];"
                 : "=r"(r[0]), "=r"(r[1]), "=r"(r[2]), "=r"(r[3]) : "r"(addr));
}
__device__ __forceinline__ void hmma(float (&d)[4], const uint32_t (&a)[4],
                                     uint32_t b0, uint32_t b1) {
    asm volatile("mma.sync.aligned.m16n8k16.row.col.f32.f16.f16.f32 "
                 "{%0,%1,%2,%3}, {%4,%5,%6,%7}, {%8,%9}, {%0,%1,%2,%3};"
                 : "+f"(d[0]), "+f"(d[1]), "+f"(d[2]), "+f"(d[3])
                 : "r"(a[0]), "r"(a[1]), "r"(a[2]), "r"(a[3]), "r"(b0), "r"(b1));
}
#define MBAR_INIT(a, c) asm volatile("mbarrier.init.shared.b64 [%0], %1;" :: "r"(a), "r"(c) : "memory")
#define MBAR_EXPECT_TX(a, n) \
    asm volatile("mbarrier.arrive.expect_tx.shared.b64 _, [%0], %1;" :: "r"(a), "r"(n) : "memory")
#define MBAR_WAIT(a, ph) do {                                                                  \
    uint32_t _m = (a), _p = (ph), _d;                                                          \
    asm volatile("{\n\t.reg .pred p;\n\t"                                                      \
        "mbarrier.try_wait.parity.acquire.cta.shared::cta.b64 p, [%1], %2;\n\t"                \
        "selp.b32 %0, 1, 0, p;\n\t}" : "=r"(_d) : "r"(_m), "r"(_p) : "memory");                \
    if (!_d) {                                                                                 \
        asm volatile("{\n\t.reg .pred P1;\n\tWL%=: \n\t"                                       \
            "mbarrier.try_wait.parity.acquire.cta.shared::cta.b64 P1, [%0], %1, 0x989680;\n\t" \
            "@P1 bra.uni WD%=;\n\tbra.uni WL%=;\n\tWD%=:\n\t}"                                 \
            :: "r"(_m), "r"(_p) : "memory");                                                   \
    } } while (0)
__device__ __forceinline__ void bulk_ld(uint32_t dst, const void* src, uint32_t bytes,
                                        uint32_t mbar) {
    asm volatile("cp.async.bulk.shared::cta.global.mbarrier::complete_tx::bytes "
                 "[%0], [%1], %2, [%3];"
                 :: "r"(dst), "l"(src), "r"(bytes), "r"(mbar) : "memory");
}
__device__ __forceinline__ unsigned f2ord(float f) {
    unsigned u = __float_as_uint(f);
    return (u & 0x80000000u) ? ~u : (u | 0x80000000u);
}
__device__ __forceinline__ float ord2f(unsigned o) {
    unsigned u = (o & 0x80000000u) ? (o & 0x7FFFFFFFu) : ~o;
    return __uint_as_float(u);
}

// ---------------- k0: init minmax + zero the 28 pad rows of every B chunk/seg ----------------
__global__ void k0_init() {
    int idx = blockIdx.x * blockDim.x + threadIdx.x;
    if (idx < CATDIM) { g_mn_bits[idx] = 0xFFFFFFFFu; g_mx_bits[idx] = 0u; }
    const int total = NCHUNK * 16 * 28;  // 16B units
    for (int id = idx; id < total; id += gridDim.x * blockDim.x) {
        int chunk = id / 448;
        int r = id % 448;
        int s = r / 28;
        int c = 260 + r % 28;
        *(uint4*)&g_Bk[(size_t)chunk * BCHUNK + ((size_t)s * NB + c) * 16] =
            make_uint4(0, 0, 0, 0);
    }
}

// ---------------- k1: t[n, h*128+k] = node @ W1[h] + b1[h] (fp32) ----------------
__global__ __launch_bounds__(256) void k1_node_transform(
    const float* __restrict__ node, const float* __restrict__ W1,
    const float* __restrict__ b1)
{
    __shared__ float As[16][64];
    __shared__ float Bs[16][64];
    const int t = threadIdx.x;
    const int n0 = blockIdx.x * 64;
    const int c0 = blockIdx.y * 64;
    const int h = c0 >> 7;
    const int k0 = c0 & 127;
    const int ty = t >> 4, tx = t & 15;
    float acc[4][4];
#pragma unroll
    for (int i = 0; i < 4; ++i)
#pragma unroll
        for (int j = 0; j < 4; ++j) acc[i][j] = 0.f;

    for (int d0 = 0; d0 < NODE_DIM; d0 += 16) {
        {
            int n = t >> 2, dq = (t & 3) * 4;
            float4 v = *(const float4*)&node[(n0 + n) * NODE_DIM + d0 + dq];
            As[dq + 0][n] = v.x; As[dq + 1][n] = v.y;
            As[dq + 2][n] = v.z; As[dq + 3][n] = v.w;
        }
        {
            int d = t >> 4, cq = (t & 15) * 4;
            *(float4*)&Bs[d][cq] =
                *(const float4*)&W1[h * (NODE_DIM * HIDDEN) + (d0 + d) * HIDDEN + k0 + cq];
        }
        __syncthreads();
#pragma unroll
        for (int dd = 0; dd < 16; ++dd) {
            float a[4], b[4];
#pragma unroll
            for (int i = 0; i < 4; ++i) a[i] = As[dd][ty * 4 + i];
#pragma unroll
            for (int j = 0; j < 4; ++j) b[j] = Bs[dd][tx * 4 + j];
#pragma unroll
            for (int i = 0; i < 4; ++i)
#pragma unroll
                for (int j = 0; j < 4; ++j) acc[i][j] += a[i] * b[j];
        }
        __syncthreads();
    }
#pragma unroll
    for (int i = 0; i < 4; ++i)
#pragma unroll
        for (int j = 0; j < 4; ++j)
            g_t[(size_t)(n0 + ty * 4 + i) * TCOLS + c0 + tx * 4 + j] =
                acc[i][j] + b1[h * HIDDEN + k0 + tx * 4 + j];
}

// ---------------- write one split-fp16 value pair into the blocked B layout ----------------
__device__ __forceinline__ void bk_store_pair(int c, int n, float v0, float v1) {
    // n even; n, n+1 in same 16B seg
    __half h0 = __float2half_rn(v0), h1 = __float2half_rn(v1);
    __half l0 = __float2half_rn(v0 - __half2float(h0));
    __half l1 = __float2half_rn(v1 - __half2float(h1));
    int chunk = n >> 6, nin = n & 63;
    size_t base = (size_t)chunk * BCHUNK + (((size_t)(nin >> 3)) * NB + c) * 16 + (nin & 7) * 2;
    *(__half2*)&g_Bk[base] = __halves2half2(h0, h1);
    *(__half2*)&g_Bk[base + 8 * NB * 16] = __halves2half2(l0, l1);
}

// ---------------- k1b: P = t@W2, q = t.Wa; write blocked split-fp16 ----------------
__global__ __launch_bounds__(256) void k1b_project(
    const float* __restrict__ W2, const float* __restrict__ Wa)
{
    extern __shared__ float smf[];
    float* sT = smf;                 // [64][132]
    float* sW2 = smf + 64 * 132;     // [128][68]
    float* sWa = sW2 + 128 * 68;     // [128]
    const int t = threadIdx.x;
    const int n0 = blockIdx.x * 64;
    const int h = blockIdx.y;

    for (int i = t; i < 64 * 32; i += 256) {
        int n = i >> 5, k4 = (i & 31) * 4;
        *(float4*)&sT[n * 132 + k4] =
            *(const float4*)&g_t[(size_t)(n0 + n) * TCOLS + h * HIDDEN + k4];
    }
    for (int i = t; i < 128 * 16; i += 256) {
        int k = i >> 4, o4 = (i & 15) * 4;
        *(float4*)&sW2[k * 68 + o4] =
            *(const float4*)&W2[(size_t)h * HIDDEN * EDGE_DIM + k * EDGE_DIM + o4];
    }
    if (t < 128) sWa[t] = Wa[h * HIDDEN + t];
    __syncthreads();

    const int ty = t >> 4, tx = t & 15;
    float acc[4][4] = {};
    for (int k = 0; k < HIDDEN; ++k) {
        float4 w = *(const float4*)&sW2[k * 68 + tx * 4];
#pragma unroll
        for (int i = 0; i < 4; ++i) {
            float a = sT[(ty * 4 + i) * 132 + k];
            acc[i][0] += a * w.x; acc[i][1] += a * w.y;
            acc[i][2] += a * w.z; acc[i][3] += a * w.w;
        }
    }
#pragma unroll
    for (int j = 0; j < 4; ++j) {
        int c = h * EDGE_DIM + tx * 4 + j;
        bk_store_pair(c, n0 + ty * 4 + 0, acc[0][j], acc[1][j]);
        bk_store_pair(c, n0 + ty * 4 + 2, acc[2][j], acc[3][j]);
    }
    if (tx == 0) {
        int c = CATDIM + h;
        float q[4];
#pragma unroll
        for (int i = 0; i < 4; ++i) {
            int n = ty * 4 + i;
            float s = 0.f;
            for (int k = 0; k < HIDDEN; ++k) s += sT[n * 132 + k] * sWa[k];
            q[i] = s;
        }
        bk_store_pair(c, n0 + ty * 4 + 0, q[0], q[1]);
        bk_store_pair(c, n0 + ty * 4 + 2, q[2], q[3]);
    }
}

// ---------------- k2: HMMA split-fp16 GEMM (3 passes)  Mu[e, c] = incT @ [P|q] ----------------
// A split hi/lo fp16; B split hi/lo fp16; passes AhBh + AhBl + AlBh.
// CTA 128e x 288c, 512 threads (16 warps: 4m x 4n, warp tile 32x72), 2-stage, KCH=64.
// A stage: 64 k-rows x [hi 256B | lo 256B | pad 16B] = 528B -> 33792B
// B stage: one blocked chunk = 73728B (single cp.async.bulk); one ldmat4 -> hi+lo frags
#define K2_ASZ 33792
#define K2_SS (K2_ASZ + BCHUNK)  /* 107520 */
#define K2_SMEM (2 * K2_SS)      /* 215040 */

__global__ __launch_bounds__(512, 1) void k2_mma(const float* __restrict__ inc,
                                                 const float* __restrict__ ba)
{
    extern __shared__ char sm[];
    __shared__ __align__(8) unsigned long long mbar[2];
    const int t = threadIdx.x;
    const int lane = t & 31, wid = t >> 5;
    const int e0 = blockIdx.x * 128;
    const int wm0 = (wid >> 2) * 32;   // 4 warps in m
    const int wn0 = (wid & 3) * 72;    // 4 warps in n (9 mma-n tiles each)
    const uint32_t sb = smem_u32(sm);

    if (t == 0) {
        MBAR_INIT(smem_u32(&mbar[0]), 1);
        MBAR_INIT(smem_u32(&mbar[1]), 1);
    }
    __syncthreads();

    float4 rA[4];
    auto ldgA = [&](int kt) {
#pragma unroll
        for (int it = 0; it < 4; ++it) {
            int idx = t + it * 512;
            int r = idx >> 5, f = idx & 31;
            rA[it] = *(const float4*)&inc[(size_t)(kt * KCH + r) * N_EDGES + e0 + f * 4];
        }
    };
    auto stsA = [&](int s) {
        char* ab = sm + s * K2_SS;
#pragma unroll
        for (int it = 0; it < 4; ++it) {
            int idx = t + it * 512;
            int r = idx >> 5, f = idx & 31;
            float4 v = rA[it];
            __half hx = __float2half_rn(v.x), hy = __float2half_rn(v.y);
            __half hz = __float2half_rn(v.z), hw = __float2half_rn(v.w);
            __half lx = __float2half_rn(v.x - __half2float(hx));
            __half ly = __float2half_rn(v.y - __half2float(hy));
            __half lz = __float2half_rn(v.z - __half2float(hz));
            __half lw = __float2half_rn(v.w - __half2float(hw));
            uint32_t off = r * 528 + f * 8;
            *(__half2*)(ab + off)       = __halves2half2(hx, hy);
            *(__half2*)(ab + off + 4)   = __halves2half2(hz, hw);
            *(__half2*)(ab + off + 256) = __halves2half2(lx, ly);
            *(__half2*)(ab + off + 260) = __halves2half2(lz, lw);
        }
    };
    auto loadB = [&](int s, int kt) {
        if (t == 0) {
            uint32_t mb = smem_u32(&mbar[s]);
            MBAR_EXPECT_TX(mb, (uint32_t)BCHUNK);
            bulk_ld(sb + s * K2_SS + K2_ASZ, g_Bk + (size_t)kt * BCHUNK, BCHUNK, mb);
        }
    };

    float acc[2][9][4];
#pragma unroll
    for (int mt = 0; mt < 2; ++mt)
#pragma unroll
        for (int nt = 0; nt < 9; ++nt)
#pragma unroll
            for (int j = 0; j < 4; ++j) acc[mt][nt][j] = 0.f;

    // prologue: stages 0,1 <- chunks 0,1; rA <- chunk 2
    loadB(0, 0);
    loadB(1, 1);
    ldgA(0); stsA(0);
    ldgA(1); stsA(1);
    ldgA(2);

    const int grp = lane >> 3, gi = lane & 7;
    const uint32_t bLane = (wn0 + (lane & 7)) * 16 +
                           ((grp & 1) + (grp & 2) * 4) * (NB * 16);
    int ph0 = 0, ph1 = 0;
    for (int kt = 0; kt < NCHUNK; ++kt) {
        const int buf = kt & 1;
        if (buf == 0) { MBAR_WAIT(smem_u32(&mbar[0]), ph0); ph0 ^= 1; }
        else          { MBAR_WAIT(smem_u32(&mbar[1]), ph1); ph1 ^= 1; }
        __syncthreads();

        const uint32_t aBase = sb + buf * K2_SS;
        const uint32_t bBase = aBase + K2_ASZ + bLane;
#pragma unroll
        for (int kk = 0; kk < KCH; kk += 16) {
            uint32_t aH[2][4], aL[2][4];
            const int krow = kk + ((grp & 2) ? 8 : 0) + gi;
#pragma unroll
            for (int mt = 0; mt < 2; ++mt) {
                const uint32_t mcol = wm0 + mt * 16 + ((grp & 1) ? 8 : 0);
                ldmat4t(aH[mt], aBase + krow * 528 + mcol * 2);
                ldmat4t(aL[mt], aBase + krow * 528 + 256 + mcol * 2);
            }
            const uint32_t bK = bBase + (kk >> 3) * (NB * 16);  // seg 2*(kk/16)
            // process nt in groups of 3: load 3 B frags, then 18 HMMAs
#pragma unroll
            for (int g = 0; g < 3; ++g) {
                uint32_t b[3][4];  // hi-b0, hi-b1, lo-b0, lo-b1
#pragma unroll
                for (int q = 0; q < 3; ++q)
                    ldmat4(b[q], bK + (g * 3 + q) * 128);
#pragma unroll
                for (int q = 0; q < 3; ++q) {
                    const int nt = g * 3 + q;
#pragma unroll
                    for (int mt = 0; mt < 2; ++mt) {
                        hmma(acc[mt][nt], aH[mt], b[q][0], b[q][1]);
                        hmma(acc[mt][nt], aH[mt], b[q][2], b[q][3]);
                        hmma(acc[mt][nt], aL[mt], b[q][0], b[q][1]);
                    }
                }
            }
        }
        __syncthreads();
        if (kt + 2 < NCHUNK) {
            loadB(buf, kt + 2);
            stsA(buf);
            if (kt + 3 < NCHUNK) ldgA(kt + 3);
        }
    }

    // epilogue
#pragma unroll
    for (int mt = 0; mt < 2; ++mt) {
        const int e = e0 + wm0 + mt * 16 + (lane >> 2);
#pragma unroll
        for (int nt = 0; nt < 9; ++nt) {
            const int c = wn0 + nt * 8 + (lane & 3) * 2;
            if (c < CATDIM) {
                *(float2*)&g_Mu[(size_t)e * CATDIM + c] =
                    make_float2(acc[mt][nt][0], acc[mt][nt][1]);
                *(float2*)&g_Mu[(size_t)(e + 8) * CATDIM + c] =
                    make_float2(acc[mt][nt][2], acc[mt][nt][3]);
            } else if (c < CATDIM + HEADS) {
                const int h0 = c - CATDIM;
                float b0 = ba[h0], b1 = ba[h0 + 1];
                float s0 = acc[mt][nt][0] + b0, s1 = acc[mt][nt][1] + b1;
                float s2 = acc[mt][nt][2] + b0, s3 = acc[mt][nt][3] + b1;
                s0 = s0 > 0.f ? s0 : 0.2f * s0;
                s1 = s1 > 0.f ? s1 : 0.2f * s1;
                s2 = s2 > 0.f ? s2 : 0.2f * s2;
                s3 = s3 > 0.f ? s3 : 0.2f * s3;
                g_score[h0 * N_EDGES + e] = s0;
                g_score[(h0 + 1) * N_EDGES + e] = s1;
                g_score[h0 * N_EDGES + e + 8] = s2;
                g_score[(h0 + 1) * N_EDGES + e + 8] = s3;
            }
        }
    }
}

// ---------------- k4: softmax over edges, per head ----------------
__global__ void k4_softmax()
{
    __shared__ float red[1024];
    const int h = blockIdx.x;
    const int t = threadIdx.x;
    const float* srow = &g_score[h * N_EDGES];

    float m = -3.4e38f;
    for (int i = t; i < N_EDGES; i += 1024) m = fmaxf(m, srow[i]);
    red[t] = m;
    __syncthreads();
    for (int s = 512; s > 0; s >>= 1) {
        if (t < s) red[t] = fmaxf(red[t], red[t + s]);
        __syncthreads();
    }
    m = red[0];
    __syncthreads();

    float sum = 0.f;
    for (int i = t; i < N_EDGES; i += 1024) sum += expf(srow[i] - m);
    red[t] = sum;
    __syncthreads();
    for (int s = 512; s > 0; s >>= 1) {
        if (t < s) red[t] += red[t + s];
        __syncthreads();
    }
    float inv = 1.0f / red[0];

    for (int i = t; i < N_EDGES; i += 1024)
        g_coeff[h * N_EDGES + i] = expf(srow[i] - m) * inv;
}

// ---------------- k5: u = coeff*Mu + b2 ; column min/max ----------------
__global__ __launch_bounds__(256) void k5_u(const float* __restrict__ b2)
{
    const int c = threadIdx.x;
    const int e0 = blockIdx.x * 64;
    const int h = c >> 6;
    const float bb = b2[c];
    float mn = 3.4e38f, mx = -3.4e38f;
    for (int i = 0; i < 64; ++i) {
        int e = e0 + i;
        float u = g_coeff[h * N_EDGES + e] * g_Mu[(size_t)e * CATDIM + c] + bb;
        g_U[(size_t)e * CATDIM + c] = u;
        mn = fminf(mn, u); mx = fmaxf(mx, u);
    }
    atomicMin(&g_mn_bits[c], f2ord(mn));
    atomicMax(&g_mx_bits[c], f2ord(mx));
}

// ---------------- k6: out = relu(minmax_norm(U)) @ Wout + bout ----------------
__global__ __launch_bounds__(256) void k6_out(const float* __restrict__ Wout,
                                              const float* __restrict__ bout,
                                              float* __restrict__ out)
{
    __shared__ float sX[32 * CATDIM];
    __shared__ float sMin[CATDIM];
    __shared__ float sInv[CATDIM];
    const int t = threadIdx.x;
    const int e0 = blockIdx.x * 32;

    for (int i = t; i < CATDIM; i += 256) {
        float mn = ord2f(g_mn_bits[i]);
        float mx = ord2f(g_mx_bits[i]);
        sMin[i] = mn;
        sInv[i] = 1.0f / (mx - mn + 1e-8f);
    }
    __syncthreads();
    for (int i = t; i < 32 * CATDIM / 4; i += 256) {
        int l = i * 4; int e = l >> 8; int c = l & 255;
        float4 v = *(const float4*)&g_U[(size_t)(e0 + e) * CATDIM + c];
        v.x = fmaxf((v.x - sMin[c + 0]) * sInv[c + 0], 0.f);
        v.y = fmaxf((v.y - sMin[c + 1]) * sInv[c + 1], 0.f);
        v.z = fmaxf((v.z - sMin[c + 2]) * sInv[c + 2], 0.f);
        v.w = fmaxf((v.w - sMin[c + 3]) * sInv[c + 3], 0.f);
        *(float4*)&sX[l] = v;
    }
    __syncthreads();

    const int ty = t >> 4, tx = t & 15;
    float acc[2][4] = {{0.f,0.f,0.f,0.f},{0.f,0.f,0.f,0.f}};
#pragma unroll 4
    for (int c = 0; c < CATDIM; ++c) {
        float4 w = *(const float4*)&Wout[c * OUT_DIM + tx * 4];
#pragma unroll
        for (int ee = 0; ee < 2; ++ee) {
            float xv = sX[(ty + ee * 16) * CATDIM + c];
            acc[ee][0] += xv * w.x; acc[ee][1] += xv * w.y;
            acc[ee][2] += xv * w.z; acc[ee][3] += xv * w.w;
        }
    }
    float4 bo = *(const float4*)&bout[tx * 4];
#pragma unroll
    for (int ee = 0; ee < 2; ++ee) {
        int e = e0 + ty + ee * 16;
        out[(size_t)e * OUT_DIM + tx * 4 + 0] = acc[ee][0] + bo.x;
        out[(size_t)e * OUT_DIM + tx * 4 + 1] = acc[ee][1] + bo.y;
        out[(size_t)e * OUT_DIM + tx * 4 + 2] = acc[ee][2] + bo.z;
        out[(size_t)e * OUT_DIM + tx * 4 + 3] = acc[ee][3] + bo.w;
    }
}

// ---------------- launch ----------------
extern "C" void kernel_launch(void* const* d_in, const int* in_sizes, int n_in,
                              void* d_out, int out_size)
{
    (void)in_sizes; (void)n_in; (void)out_size;
    const float* node = (const float*)d_in[0];
    const float* inc  = (const float*)d_in[1];
    const float* W1   = (const float*)d_in[2];
    const float* b1   = (const float*)d_in[3];
    const float* Wa   = (const float*)d_in[4];
    const float* ba   = (const float*)d_in[5];
    const float* W2   = (const float*)d_in[6];
    const float* b2   = (const float*)d_in[7];
    const float* Wout = (const float*)d_in[8];
    const float* bout = (const float*)d_in[9];
    float* out = (float*)d_out;

    cudaFuncSetAttribute(k2_mma, cudaFuncAttributeMaxDynamicSharedMemorySize, K2_SMEM);
    cudaFuncSetAttribute(k1b_project, cudaFuncAttributeMaxDynamicSharedMemorySize, 69120);

    k0_init<<<64, 256>>>();
    k1_node_transform<<<dim3(N_NODES / 64, TCOLS / 64), 256>>>(node, W1, b1);
    k1b_project<<<dim3(N_NODES / 64, HEADS), 256, 69120>>>(W2, Wa);
    k2_mma<<<N_EDGES / 128, 512, K2_SMEM>>>(inc, ba);
    k4_softmax<<<HEADS, 1024>>>();
    k5_u<<<N_EDGES / 64, 256>>>(b2);
    k6_out<<<N_EDGES / 32, 256>>>(Wout, bout, out);
}

// round 13
// speedup vs baseline: 1.6350x; 1.0014x over previous
#include <cuda_runtime.h>
#include <cuda_fp16.h>
#include <cstdint>
#include <cstddef>

#define N_NODES 4096
#define N_EDGES 16384
#define NODE_DIM 128
#define HIDDEN 128
#define EDGE_DIM 64
#define HEADS 4
#define OUT_DIM 64
#define TCOLS (HEADS * HIDDEN)    /* 512 */
#define CATDIM (HEADS * EDGE_DIM) /* 256 */
#define NB 264                    /* B rows: 256 P + 4 q + 4 zero pad */
#define KCH 64                    /* k per chunk */
#define NCHUNK (N_NODES / KCH)    /* 64 */
#define BCHUNK (NB * 256)         /* bytes per B chunk: 264 rows x (128 hi + 128 lo) = 67584 */

// ---------------- scratch (static device globals; no allocation) ----------------
__device__ __align__(16) float g_t[(size_t)N_NODES * TCOLS];          // 8 MB
// blocked split-fp16 B: [chunk][seg 0..15][c 0..263][16B]; seg 0-7 = hi k-groups, 8-15 = lo
__device__ __align__(16) char g_Bk[(size_t)NCHUNK * BCHUNK];          // 4.3 MB
__device__ __align__(16) float g_Mu[(size_t)N_EDGES * CATDIM];        // 16.8 MB
__device__ __align__(16) float g_score[HEADS * N_EDGES];
__device__ __align__(16) float g_coeff[HEADS * N_EDGES];
__device__ __align__(16) float g_U[(size_t)N_EDGES * CATDIM];         // 16.8 MB
__device__ unsigned g_mn_bits[CATDIM];
__device__ unsigned g_mx_bits[CATDIM];

// ---------------- helpers ----------------
__device__ __forceinline__ uint32_t smem_u32(const void* p) {
    uint32_t a;
    asm("{ .reg .u64 t; cvta.to.shared.u64 t, %1; cvt.u32.u64 %0, t; }" : "=r"(a) : "l"(p));
    return a;
}
__device__ __forceinline__ void ldmat4t(uint32_t (&r)[4], uint32_t addr) {
    asm volatile("ldmatrix.sync.aligned.m8n8.x4.trans.shared.b16 {%0,%1,%2,%3}, [%4];"
                 : "=r"(r[0]), "=r"(r[1]), "=r"(r[2]), "=r"(r[3]) : "r"(addr));
}
__device__ __forceinline__ void ldmat4(uint32_t (&r)[4], uint32_t addr) {
    asm volatile("ldmatrix.sync.aligned.m8n8.x4.shared.b16 {%0,%1,%2,%3}, [%4];"
                 : "=r"(r[0]), "=r"(r[1]), "=r"(r[2]), "=r"(r[3]) : "r"(addr));
}
__device__ __forceinline__ void hmma(float (&d)[4], const uint32_t (&a)[4],
                                     uint32_t b0, uint32_t b1) {
    asm volatile("mma.sync.aligned.m16n8k16.row.col.f32.f16.f16.f32 "
                 "{%0,%1,%2,%3}, {%4,%5,%6,%7}, {%8,%9}, {%0,%1,%2,%3};"
                 : "+f"(d[0]), "+f"(d[1]), "+f"(d[2]), "+f"(d[3])
                 : "r"(a[0]), "r"(a[1]), "r"(a[2]), "r"(a[3]), "r"(b0), "r"(b1));
}
#define MBAR_INIT(a, c) asm volatile("mbarrier.init.shared.b64 [%0], %1;" :: "r"(a), "r"(c) : "memory")
#define MBAR_EXPECT_TX(a, n) \
    asm volatile("mbarrier.arrive.expect_tx.shared.b64 _, [%0], %1;" :: "r"(a), "r"(n) : "memory")
#define MBAR_WAIT(a, ph) do {                                                                  \
    uint32_t _m = (a), _p = (ph), _d;                                                          \
    asm volatile("{\n\t.reg .pred p;\n\t"                                                      \
        "mbarrier.try_wait.parity.acquire.cta.shared::cta.b64 p, [%1], %2;\n\t"                \
        "selp.b32 %0, 1, 0, p;\n\t}" : "=r"(_d) : "r"(_m), "r"(_p) : "memory");                \
    if (!_d) {                                                                                 \
        asm volatile("{\n\t.reg .pred P1;\n\tWL%=: \n\t"                                       \
            "mbarrier.try_wait.parity.acquire.cta.shared::cta.b64 P1, [%0], %1, 0x989680;\n\t" \
            "@P1 bra.uni WD%=;\n\tbra.uni WL%=;\n\tWD%=:\n\t}"                                 \
            :: "r"(_m), "r"(_p) : "memory");                                                   \
    } } while (0)
__device__ __forceinline__ void bulk_ld(uint32_t dst, const void* src, uint32_t bytes,
                                        uint32_t mbar) {
    asm volatile("cp.async.bulk.shared::cta.global.mbarrier::complete_tx::bytes "
                 "[%0], [%1], %2, [%3];"
                 :: "r"(dst), "l"(src), "r"(bytes), "r"(mbar) : "memory");
}
__device__ __forceinline__ unsigned f2ord(float f) {
    unsigned u = __float_as_uint(f);
    return (u & 0x80000000u) ? ~u : (u | 0x80000000u);
}
__device__ __forceinline__ float ord2f(unsigned o) {
    unsigned u = (o & 0x80000000u) ? (o & 0x7FFFFFFFu) : ~o;
    return __uint_as_float(u);
}

// ---------------- k0: init minmax + zero the 4 pad rows of every B chunk/seg ----------------
__global__ void k0_init() {
    int idx = blockIdx.x * blockDim.x + threadIdx.x;
    if (idx < CATDIM) { g_mn_bits[idx] = 0xFFFFFFFFu; g_mx_bits[idx] = 0u; }
    const int total = NCHUNK * 16 * 4;  // 16B units
    for (int id = idx; id < total; id += gridDim.x * blockDim.x) {
        int chunk = id / 64;
        int r = id % 64;
        int s = r / 4;
        int c = 260 + (r & 3);
        *(uint4*)&g_Bk[(size_t)chunk * BCHUNK + ((size_t)s * NB + c) * 16] =
            make_uint4(0, 0, 0, 0);
    }
}

// ---------------- k1: t[n, h*128+k] = node @ W1[h] + b1[h] (fp32) ----------------
__global__ __launch_bounds__(256) void k1_node_transform(
    const float* __restrict__ node, const float* __restrict__ W1,
    const float* __restrict__ b1)
{
    __shared__ float As[16][64];
    __shared__ float Bs[16][64];
    const int t = threadIdx.x;
    const int n0 = blockIdx.x * 64;
    const int c0 = blockIdx.y * 64;
    const int h = c0 >> 7;
    const int k0 = c0 & 127;
    const int ty = t >> 4, tx = t & 15;
    float acc[4][4];
#pragma unroll
    for (int i = 0; i < 4; ++i)
#pragma unroll
        for (int j = 0; j < 4; ++j) acc[i][j] = 0.f;

    for (int d0 = 0; d0 < NODE_DIM; d0 += 16) {
        {
            int n = t >> 2, dq = (t & 3) * 4;
            float4 v = *(const float4*)&node[(n0 + n) * NODE_DIM + d0 + dq];
            As[dq + 0][n] = v.x; As[dq + 1][n] = v.y;
            As[dq + 2][n] = v.z; As[dq + 3][n] = v.w;
        }
        {
            int d = t >> 4, cq = (t & 15) * 4;
            *(float4*)&Bs[d][cq] =
                *(const float4*)&W1[h * (NODE_DIM * HIDDEN) + (d0 + d) * HIDDEN + k0 + cq];
        }
        __syncthreads();
#pragma unroll
        for (int dd = 0; dd < 16; ++dd) {
            float a[4], b[4];
#pragma unroll
            for (int i = 0; i < 4; ++i) a[i] = As[dd][ty * 4 + i];
#pragma unroll
            for (int j = 0; j < 4; ++j) b[j] = Bs[dd][tx * 4 + j];
#pragma unroll
            for (int i = 0; i < 4; ++i)
#pragma unroll
                for (int j = 0; j < 4; ++j) acc[i][j] += a[i] * b[j];
        }
        __syncthreads();
    }
#pragma unroll
    for (int i = 0; i < 4; ++i)
#pragma unroll
        for (int j = 0; j < 4; ++j)
            g_t[(size_t)(n0 + ty * 4 + i) * TCOLS + c0 + tx * 4 + j] =
                acc[i][j] + b1[h * HIDDEN + k0 + tx * 4 + j];
}

// ---------------- write one split-fp16 value pair into the blocked B layout ----------------
__device__ __forceinline__ void bk_store_pair(int c, int n, float v0, float v1) {
    // n even; n, n+1 in same 16B seg
    __half h0 = __float2half_rn(v0), h1 = __float2half_rn(v1);
    __half l0 = __float2half_rn(v0 - __half2float(h0));
    __half l1 = __float2half_rn(v1 - __half2float(h1));
    int chunk = n >> 6, nin = n & 63;
    size_t base = (size_t)chunk * BCHUNK + (((size_t)(nin >> 3)) * NB + c) * 16 + (nin & 7) * 2;
    *(__half2*)&g_Bk[base] = __halves2half2(h0, h1);
    *(__half2*)&g_Bk[base + 8 * NB * 16] = __halves2half2(l0, l1);
}

// ---------------- k1b: P = t@W2, q = t.Wa; write blocked split-fp16 ----------------
__global__ __launch_bounds__(256) void k1b_project(
    const float* __restrict__ W2, const float* __restrict__ Wa)
{
    extern __shared__ float smf[];
    float* sT = smf;                 // [64][132]
    float* sW2 = smf + 64 * 132;     // [128][68]
    float* sWa = sW2 + 128 * 68;     // [128]
    const int t = threadIdx.x;
    const int n0 = blockIdx.x * 64;
    const int h = blockIdx.y;

    for (int i = t; i < 64 * 32; i += 256) {
        int n = i >> 5, k4 = (i & 31) * 4;
        *(float4*)&sT[n * 132 + k4] =
            *(const float4*)&g_t[(size_t)(n0 + n) * TCOLS + h * HIDDEN + k4];
    }
    for (int i = t; i < 128 * 16; i += 256) {
        int k = i >> 4, o4 = (i & 15) * 4;
        *(float4*)&sW2[k * 68 + o4] =
            *(const float4*)&W2[(size_t)h * HIDDEN * EDGE_DIM + k * EDGE_DIM + o4];
    }
    if (t < 128) sWa[t] = Wa[h * HIDDEN + t];
    __syncthreads();

    const int ty = t >> 4, tx = t & 15;
    float acc[4][4] = {};
    for (int k = 0; k < HIDDEN; ++k) {
        float4 w = *(const float4*)&sW2[k * 68 + tx * 4];
#pragma unroll
        for (int i = 0; i < 4; ++i) {
            float a = sT[(ty * 4 + i) * 132 + k];
            acc[i][0] += a * w.x; acc[i][1] += a * w.y;
            acc[i][2] += a * w.z; acc[i][3] += a * w.w;
        }
    }
#pragma unroll
    for (int j = 0; j < 4; ++j) {
        int c = h * EDGE_DIM + tx * 4 + j;
        bk_store_pair(c, n0 + ty * 4 + 0, acc[0][j], acc[1][j]);
        bk_store_pair(c, n0 + ty * 4 + 2, acc[2][j], acc[3][j]);
    }
    if (tx == 0) {
        int c = CATDIM + h;
        float q[4];
#pragma unroll
        for (int i = 0; i < 4; ++i) {
            int n = ty * 4 + i;
            float s = 0.f;
            for (int k = 0; k < HIDDEN; ++k) s += sT[n * 132 + k] * sWa[k];
            q[i] = s;
        }
        bk_store_pair(c, n0 + ty * 4 + 0, q[0], q[1]);
        bk_store_pair(c, n0 + ty * 4 + 2, q[2], q[3]);
    }
}

// ---------------- k2: HMMA split-fp16 GEMM (3 passes)  Mu[e, c] = incT @ [P|q] ----------------
// A split hi/lo fp16; B split hi/lo fp16; passes AhBh + AhBl + AlBh.
// CTA 128e x 264c, 640 threads (20 warps: 4m x 5n), 2-stage, KCH=64, one sync/chunk.
// n-groups: {56,56,56,48,48}; SMSP = wid&3 so every SMSP carries one warp per n-group.
// A stage: 64 k-rows x [hi 256B | lo 256B | pad 16B] = 528B -> 33792B
// B stage: one blocked chunk = 67584B (single cp.async.bulk); one ldmat4 -> hi+lo frags
#define K2_ASZ 33792
#define K2_SS (K2_ASZ + BCHUNK)  /* 101376 */
#define K2_SMEM (2 * K2_SS)      /* 202752 */

__global__ __launch_bounds__(640, 1) void k2_mma(const float* __restrict__ inc,
                                                 const float* __restrict__ ba)
{
    extern __shared__ char sm[];
    __shared__ __align__(8) unsigned long long mbar[2];
    const int t = threadIdx.x;
    const int lane = t & 31, wid = t >> 5;
    const int e0 = blockIdx.x * 128;
    const int mg = wid & 3;            // m-group -> SMSP id
    const int ng = wid >> 2;           // n-group 0..4
    const int wm0 = mg * 32;
    const int wn0 = (ng < 3) ? ng * 56 : 168 + (ng - 3) * 48;
    const int ntcnt = (ng < 3) ? 7 : 6;
    const uint32_t sb = smem_u32(sm);

    if (t == 0) {
        MBAR_INIT(smem_u32(&mbar[0]), 1);
        MBAR_INIT(smem_u32(&mbar[1]), 1);
    }

    float4 rA[4];
    auto ldgA = [&](int kt) {
        if (t < 512) {
#pragma unroll
            for (int it = 0; it < 4; ++it) {
                int idx = t + it * 512;
                int r = idx >> 5, f = idx & 31;
                rA[it] = *(const float4*)&inc[(size_t)(kt * KCH + r) * N_EDGES + e0 + f * 4];
            }
        }
    };
    auto stsA = [&](int s) {
        if (t < 512) {
            char* ab = sm + s * K2_SS;
#pragma unroll
            for (int it = 0; it < 4; ++it) {
                int idx = t + it * 512;
                int r = idx >> 5, f = idx & 31;
                float4 v = rA[it];
                __half hx = __float2half_rn(v.x), hy = __float2half_rn(v.y);
                __half hz = __float2half_rn(v.z), hw = __float2half_rn(v.w);
                __half lx = __float2half_rn(v.x - __half2float(hx));
                __half ly = __float2half_rn(v.y - __half2float(hy));
                __half lz = __float2half_rn(v.z - __half2float(hz));
                __half lw = __float2half_rn(v.w - __half2float(hw));
                uint32_t off = r * 528 + f * 8;
                *(__half2*)(ab + off)       = __halves2half2(hx, hy);
                *(__half2*)(ab + off + 4)   = __halves2half2(hz, hw);
                *(__half2*)(ab + off + 256) = __halves2half2(lx, ly);
                *(__half2*)(ab + off + 260) = __halves2half2(lz, lw);
            }
        }
    };
    auto loadB = [&](int s, int kt) {
        if (t == 0) {
            uint32_t mb = smem_u32(&mbar[s]);
            MBAR_EXPECT_TX(mb, (uint32_t)BCHUNK);
            bulk_ld(sb + s * K2_SS + K2_ASZ, g_Bk + (size_t)kt * BCHUNK, BCHUNK, mb);
        }
    };

    float acc[2][7][4];
#pragma unroll
    for (int mt = 0; mt < 2; ++mt)
#pragma unroll
        for (int nt = 0; nt < 7; ++nt)
#pragma unroll
            for (int j = 0; j < 4; ++j) acc[mt][nt][j] = 0.f;

    // prologue: mbar init visible, then stages 0,1 <- chunks 0,1; rA <- chunk 2
    __syncthreads();
    loadB(0, 0);
    loadB(1, 1);
    ldgA(0); stsA(0);
    ldgA(1); stsA(1);
    ldgA(2);
    __syncthreads();

    const int grp = lane >> 3, gi = lane & 7;
    const uint32_t bLane = (wn0 + (lane & 7)) * 16 +
                           ((grp & 1) + (grp & 2) * 4) * (NB * 16);
    int ph0 = 0, ph1 = 0;
    for (int kt = 0; kt < NCHUNK; ++kt) {
        const int buf = kt & 1;
        if (buf == 0) { MBAR_WAIT(smem_u32(&mbar[0]), ph0); ph0 ^= 1; }
        else          { MBAR_WAIT(smem_u32(&mbar[1]), ph1); ph1 ^= 1; }

        const uint32_t aBase = sb + buf * K2_SS;
        const uint32_t bBase = aBase + K2_ASZ + bLane;
#pragma unroll
        for (int kk = 0; kk < KCH; kk += 16) {
            uint32_t aH[2][4], aL[2][4];
            const int krow = kk + ((grp & 2) ? 8 : 0) + gi;
#pragma unroll
            for (int mt = 0; mt < 2; ++mt) {
                const uint32_t mcol = wm0 + mt * 16 + ((grp & 1) ? 8 : 0);
                ldmat4t(aH[mt], aBase + krow * 528 + mcol * 2);
                ldmat4t(aL[mt], aBase + krow * 528 + 256 + mcol * 2);
            }
            const uint32_t bK = bBase + (kk >> 3) * (NB * 16);  // seg 2*(kk/16)
#pragma unroll
            for (int nt = 0; nt < 7; ++nt) {
                if (nt < ntcnt) {
                    uint32_t b[4];  // hi-b0, hi-b1, lo-b0, lo-b1
                    ldmat4(b, bK + nt * 128);
#pragma unroll
                    for (int mt = 0; mt < 2; ++mt) {
                        hmma(acc[mt][nt], aH[mt], b[0], b[1]);
                        hmma(acc[mt][nt], aH[mt], b[2], b[3]);
                        hmma(acc[mt][nt], aL[mt], b[0], b[1]);
                    }
                }
            }
        }
        __syncthreads();   // all reads of stage buf done; safe to refill
        if (kt + 2 < NCHUNK) {
            loadB(buf, kt + 2);
            stsA(buf);
            if (kt + 3 < NCHUNK) ldgA(kt + 3);
        }
    }

    // epilogue
#pragma unroll
    for (int mt = 0; mt < 2; ++mt) {
        const int e = e0 + wm0 + mt * 16 + (lane >> 2);
#pragma unroll
        for (int nt = 0; nt < 7; ++nt) {
            if (nt < ntcnt) {
                const int c = wn0 + nt * 8 + (lane & 3) * 2;
                if (c < CATDIM) {
                    *(float2*)&g_Mu[(size_t)e * CATDIM + c] =
                        make_float2(acc[mt][nt][0], acc[mt][nt][1]);
                    *(float2*)&g_Mu[(size_t)(e + 8) * CATDIM + c] =
                        make_float2(acc[mt][nt][2], acc[mt][nt][3]);
                } else if (c < CATDIM + HEADS) {
                    const int h0 = c - CATDIM;
                    float b0 = ba[h0], b1 = ba[h0 + 1];
                    float s0 = acc[mt][nt][0] + b0, s1 = acc[mt][nt][1] + b1;
                    float s2 = acc[mt][nt][2] + b0, s3 = acc[mt][nt][3] + b1;
                    s0 = s0 > 0.f ? s0 : 0.2f * s0;
                    s1 = s1 > 0.f ? s1 : 0.2f * s1;
                    s2 = s2 > 0.f ? s2 : 0.2f * s2;
                    s3 = s3 > 0.f ? s3 : 0.2f * s3;
                    g_score[h0 * N_EDGES + e] = s0;
                    g_score[(h0 + 1) * N_EDGES + e] = s1;
                    g_score[h0 * N_EDGES + e + 8] = s2;
                    g_score[(h0 + 1) * N_EDGES + e + 8] = s3;
                }
            }
        }
    }
}

// ---------------- k4: softmax over edges, per head ----------------
__global__ void k4_softmax()
{
    __shared__ float red[1024];
    const int h = blockIdx.x;
    const int t = threadIdx.x;
    const float* srow = &g_score[h * N_EDGES];

    float m = -3.4e38f;
    for (int i = t; i < N_EDGES; i += 1024) m = fmaxf(m, srow[i]);
    red[t] = m;
    __syncthreads();
    for (int s = 512; s > 0; s >>= 1) {
        if (t < s) red[t] = fmaxf(red[t], red[t + s]);
        __syncthreads();
    }
    m = red[0];
    __syncthreads();

    float sum = 0.f;
    for (int i = t; i < N_EDGES; i += 1024) sum += expf(srow[i] - m);
    red[t] = sum;
    __syncthreads();
    for (int s = 512; s > 0; s >>= 1) {
        if (t < s) red[t] += red[t + s];
        __syncthreads();
    }
    float inv = 1.0f / red[0];

    for (int i = t; i < N_EDGES; i += 1024)
        g_coeff[h * N_EDGES + i] = expf(srow[i] - m) * inv;
}

// ---------------- k5: u = coeff*Mu + b2 ; column min/max ----------------
__global__ __launch_bounds__(256) void k5_u(const float* __restrict__ b2)
{
    const int c = threadIdx.x;
    const int e0 = blockIdx.x * 64;
    const int h = c >> 6;
    const float bb = b2[c];
    float mn = 3.4e38f, mx = -3.4e38f;
    for (int i = 0; i < 64; ++i) {
        int e = e0 + i;
        float u = g_coeff[h * N_EDGES + e] * g_Mu[(size_t)e * CATDIM + c] + bb;
        g_U[(size_t)e * CATDIM + c] = u;
        mn = fminf(mn, u); mx = fmaxf(mx, u);
    }
    atomicMin(&g_mn_bits[c], f2ord(mn));
    atomicMax(&g_mx_bits[c], f2ord(mx));
}

// ---------------- k6: out = relu(minmax_norm(U)) @ Wout + bout ----------------
__global__ __launch_bounds__(256) void k6_out(const float* __restrict__ Wout,
                                              const float* __restrict__ bout,
                                              float* __restrict__ out)
{
    __shared__ float sX[32 * CATDIM];
    __shared__ float sMin[CATDIM];
    __shared__ float sInv[CATDIM];
    const int t = threadIdx.x;
    const int e0 = blockIdx.x * 32;

    for (int i = t; i < CATDIM; i += 256) {
        float mn = ord2f(g_mn_bits[i]);
        float mx = ord2f(g_mx_bits[i]);
        sMin[i] = mn;
        sInv[i] = 1.0f / (mx - mn + 1e-8f);
    }
    __syncthreads();
    for (int i = t; i < 32 * CATDIM / 4; i += 256) {
        int l = i * 4; int e = l >> 8; int c = l & 255;
        float4 v = *(const float4*)&g_U[(size_t)(e0 + e) * CATDIM + c];
        v.x = fmaxf((v.x - sMin[c + 0]) * sInv[c + 0], 0.f);
        v.y = fmaxf((v.y - sMin[c + 1]) * sInv[c + 1], 0.f);
        v.z = fmaxf((v.z - sMin[c + 2]) * sInv[c + 2], 0.f);
        v.w = fmaxf((v.w - sMin[c + 3]) * sInv[c + 3], 0.f);
        *(float4*)&sX[l] = v;
    }
    __syncthreads();

    const int ty = t >> 4, tx = t & 15;
    float acc[2][4] = {{0.f,0.f,0.f,0.f},{0.f,0.f,0.f,0.f}};
#pragma unroll 4
    for (int c = 0; c < CATDIM; ++c) {
        float4 w = *(const float4*)&Wout[c * OUT_DIM + tx * 4];
#pragma unroll
        for (int ee = 0; ee < 2; ++ee) {
            float xv = sX[(ty + ee * 16) * CATDIM + c];
            acc[ee][0] += xv * w.x; acc[ee][1] += xv * w.y;
            acc[ee][2] += xv * w.z; acc[ee][3] += xv * w.w;
        }
    }
    float4 bo = *(const float4*)&bout[tx * 4];
#pragma unroll
    for (int ee = 0; ee < 2; ++ee) {
        int e = e0 + ty + ee * 16;
        out[(size_t)e * OUT_DIM + tx * 4 + 0] = acc[ee][0] + bo.x;
        out[(size_t)e * OUT_DIM + tx * 4 + 1] = acc[ee][1] + bo.y;
        out[(size_t)e * OUT_DIM + tx * 4 + 2] = acc[ee][2] + bo.z;
        out[(size_t)e * OUT_DIM + tx * 4 + 3] = acc[ee][3] + bo.w;
    }
}

// ---------------- launch ----------------
extern "C" void kernel_launch(void* const* d_in, const int* in_sizes, int n_in,
                              void* d_out, int out_size)
{
    (void)in_sizes; (void)n_in; (void)out_size;
    const float* node = (const float*)d_in[0];
    const float* inc  = (const float*)d_in[1];
    const float* W1   = (const float*)d_in[2];
    const float* b1   = (const float*)d_in[3];
    const float* Wa   = (const float*)d_in[4];
    const float* ba   = (const float*)d_in[5];
    const float* W2   = (const float*)d_in[6];
    const float* b2   = (const float*)d_in[7];
    const float* Wout = (const float*)d_in[8];
    const float* bout = (const float*)d_in[9];
    float* out = (float*)d_out;

    cudaFuncSetAttribute(k2_mma, cudaFuncAttributeMaxDynamicSharedMemorySize, K2_SMEM);
    cudaFuncSetAttribute(k1b_project, cudaFuncAttributeMaxDynamicSharedMemorySize, 69120);

    k0_init<<<64, 256>>>();
    k1_node_transform<<<dim3(N_NODES / 64, TCOLS / 64), 256>>>(node, W1, b1);
    k1b_project<<<dim3(N_NODES / 64, HEADS), 256, 69120>>>(W2, Wa);
    k2_mma<<<N_EDGES / 128, 640, K2_SMEM>>>(inc, ba);
    k4_softmax<<<HEADS, 1024>>>();
    k5_u<<<N_EDGES / 64, 256>>>(b2);
    k6_out<<<N_EDGES / 32, 256>>>(Wout, bout, out);
}

// round 17
// speedup vs baseline: 1.9334x; 1.1825x over previous
#include <cuda_runtime.h>
#include <cuda_fp16.h>
#include <cstdint>
#include <cstddef>

#define N_NODES 4096
#define N_EDGES 16384
#define NODE_DIM 128
#define HIDDEN 128
#define EDGE_DIM 64
#define HEADS 4
#define OUT_DIM 64
#define TCOLS (HEADS * HIDDEN)    /* 512 */
#define CATDIM (HEADS * EDGE_DIM) /* 256 */
#define NB 264                    /* B rows: 256 P + 4 q + 4 zero pad */
#define KCH 64                    /* k per chunk */
#define NCHUNK (N_NODES / KCH)    /* 64 */
#define BCHUNK (NB * 256)         /* bytes per B chunk: 264 rows x (128 hi + 128 lo) = 67584 */

// ---------------- scratch (static device globals; no allocation) ----------------
__device__ __align__(16) float g_t[(size_t)N_NODES * TCOLS];          // 8 MB
// blocked split-fp16 B: [chunk][seg 0..15][c 0..263][16B]; seg 0-7 = hi k-groups, 8-15 = lo
__device__ __align__(16) char g_Bk[(size_t)NCHUNK * BCHUNK];          // 4.3 MB
__device__ __align__(16) float g_Mu[(size_t)N_EDGES * CATDIM];        // 16.8 MB
__device__ __align__(16) float g_score[HEADS * N_EDGES];
__device__ __align__(16) float g_coeff[HEADS * N_EDGES];
__device__ __align__(16) float g_U[(size_t)N_EDGES * CATDIM];         // 16.8 MB
__device__ unsigned g_mn_bits[CATDIM];
__device__ unsigned g_mx_bits[CATDIM];

// ---------------- helpers ----------------
__device__ __forceinline__ uint32_t smem_u32(const void* p) {
    uint32_t a;
    asm("{ .reg .u64 t; cvta.to.shared.u64 t, %1; cvt.u32.u64 %0, t; }" : "=r"(a) : "l"(p));
    return a;
}
__device__ __forceinline__ uint32_t lds32(uint32_t a) {
    uint32_t v;
    asm volatile("ld.shared.b32 %0, [%1];" : "=r"(v) : "r"(a));
    return v;
}
__device__ __forceinline__ void ldmat4t(uint32_t (&r)[4], uint32_t addr) {
    asm volatile("ldmatrix.sync.aligned.m8n8.x4.trans.shared.b16 {%0,%1,%2,%3}, [%4];"
                 : "=r"(r[0]), "=r"(r[1]), "=r"(r[2]), "=r"(r[3]) : "r"(addr));
}
__device__ __forceinline__ void hmma(float (&d)[4], const uint32_t (&a)[4],
                                     uint32_t b0, uint32_t b1) {
    asm volatile("mma.sync.aligned.m16n8k16.row.col.f32.f16.f16.f32 "
                 "{%0,%1,%2,%3}, {%4,%5,%6,%7}, {%8,%9}, {%0,%1,%2,%3};"
                 : "+f"(d[0]), "+f"(d[1]), "+f"(d[2]), "+f"(d[3])
                 : "r"(a[0]), "r"(a[1]), "r"(a[2]), "r"(a[3]), "r"(b0), "r"(b1));
}
#define MBAR_INIT(a, c) asm volatile("mbarrier.init.shared.b64 [%0], %1;" :: "r"(a), "r"(c) : "memory")
#define MBAR_EXPECT_TX(a, n) \
    asm volatile("mbarrier.arrive.expect_tx.shared.b64 _, [%0], %1;" :: "r"(a), "r"(n) : "memory")
#define MBAR_WAIT(a, ph) do {                                                                  \
    uint32_t _m = (a), _p = (ph), _d;                                                          \
    asm volatile("{\n\t.reg .pred p;\n\t"                                                      \
        "mbarrier.try_wait.parity.acquire.cta.shared::cta.b64 p, [%1], %2;\n\t"                \
        "selp.b32 %0, 1, 0, p;\n\t}" : "=r"(_d) : "r"(_m), "r"(_p) : "memory");                \
    if (!_d) {                                                                                 \
        asm volatile("{\n\t.reg .pred P1;\n\tWL%=: \n\t"                                       \
            "mbarrier.try_wait.parity.acquire.cta.shared::cta.b64 P1, [%0], %1, 0x989680;\n\t" \
            "@P1 bra.uni WD%=;\n\tbra.uni WL%=;\n\tWD%=:\n\t}"                                 \
            :: "r"(_m), "r"(_p) : "memory");                                                   \
    } } while (0)
__device__ __forceinline__ void bulk_ld(uint32_t dst, const void* src, uint32_t bytes,
                                        uint32_t mbar) {
    asm volatile("cp.async.bulk.shared::cta.global.mbarrier::complete_tx::bytes "
                 "[%0], [%1], %2, [%3];"
                 :: "r"(dst), "l"(src), "r"(bytes), "r"(mbar) : "memory");
}
__device__ __forceinline__ unsigned f2ord(float f) {
    unsigned u = __float_as_uint(f);
    return (u & 0x80000000u) ? ~u : (u | 0x80000000u);
}
__device__ __forceinline__ float ord2f(unsigned o) {
    unsigned u = (o & 0x80000000u) ? (o & 0x7FFFFFFFu) : ~o;
    return __uint_as_float(u);
}

// ---------------- k0: init minmax + zero the 4 pad rows of every B chunk/seg ----------------
__global__ void k0_init() {
    int idx = blockIdx.x * blockDim.x + threadIdx.x;
    if (idx < CATDIM) { g_mn_bits[idx] = 0xFFFFFFFFu; g_mx_bits[idx] = 0u; }
    const int total = NCHUNK * 16 * 4;  // 16B units
    for (int id = idx; id < total; id += gridDim.x * blockDim.x) {
        int chunk = id / 64;
        int r = id % 64;
        int s = r / 4;
        int c = 260 + (r & 3);
        *(uint4*)&g_Bk[(size_t)chunk * BCHUNK + ((size_t)s * NB + c) * 16] =
            make_uint4(0, 0, 0, 0);
    }
}

// ---------------- k1: t[n, h*128+k] = node @ W1[h] + b1[h] (fp32) ----------------
__global__ __launch_bounds__(256) void k1_node_transform(
    const float* __restrict__ node, const float* __restrict__ W1,
    const float* __restrict__ b1)
{
    __shared__ float As[16][64];
    __shared__ float Bs[16][64];
    const int t = threadIdx.x;
    const int n0 = blockIdx.x * 64;
    const int c0 = blockIdx.y * 64;
    const int h = c0 >> 7;
    const int k0 = c0 & 127;
    const int ty = t >> 4, tx = t & 15;
    float acc[4][4];
#pragma unroll
    for (int i = 0; i < 4; ++i)
#pragma unroll
        for (int j = 0; j < 4; ++j) acc[i][j] = 0.f;

    for (int d0 = 0; d0 < NODE_DIM; d0 += 16) {
        {
            int n = t >> 2, dq = (t & 3) * 4;
            float4 v = *(const float4*)&node[(n0 + n) * NODE_DIM + d0 + dq];
            As[dq + 0][n] = v.x; As[dq + 1][n] = v.y;
            As[dq + 2][n] = v.z; As[dq + 3][n] = v.w;
        }
        {
            int d = t >> 4, cq = (t & 15) * 4;
            *(float4*)&Bs[d][cq] =
                *(const float4*)&W1[h * (NODE_DIM * HIDDEN) + (d0 + d) * HIDDEN + k0 + cq];
        }
        __syncthreads();
#pragma unroll
        for (int dd = 0; dd < 16; ++dd) {
            float a[4], b[4];
#pragma unroll
            for (int i = 0; i < 4; ++i) a[i] = As[dd][ty * 4 + i];
#pragma unroll
            for (int j = 0; j < 4; ++j) b[j] = Bs[dd][tx * 4 + j];
#pragma unroll
            for (int i = 0; i < 4; ++i)
#pragma unroll
                for (int j = 0; j < 4; ++j) acc[i][j] += a[i] * b[j];
        }
        __syncthreads();
    }
#pragma unroll
    for (int i = 0; i < 4; ++i)
#pragma unroll
        for (int j = 0; j < 4; ++j)
            g_t[(size_t)(n0 + ty * 4 + i) * TCOLS + c0 + tx * 4 + j] =
                acc[i][j] + b1[h * HIDDEN + k0 + tx * 4 + j];
}

// ---------------- write one split-fp16 value pair into the blocked B layout ----------------
__device__ __forceinline__ void bk_store_pair(int c, int n, float v0, float v1) {
    // n even; n, n+1 in same 16B seg
    __half h0 = __float2half_rn(v0), h1 = __float2half_rn(v1);
    __half l0 = __float2half_rn(v0 - __half2float(h0));
    __half l1 = __float2half_rn(v1 - __half2float(h1));
    int chunk = n >> 6, nin = n & 63;
    size_t base = (size_t)chunk * BCHUNK + (((size_t)(nin >> 3)) * NB + c) * 16 + (nin & 7) * 2;
    *(__half2*)&g_Bk[base] = __halves2half2(h0, h1);
    *(__half2*)&g_Bk[base + 8 * NB * 16] = __halves2half2(l0, l1);
}

// ---------------- k1b: P = t@W2, q = t.Wa; write blocked split-fp16 ----------------
__global__ __launch_bounds__(256) void k1b_project(
    const float* __restrict__ W2, const float* __restrict__ Wa)
{
    extern __shared__ float smf[];
    float* sT = smf;                 // [64][132]
    float* sW2 = smf + 64 * 132;     // [128][68]
    float* sWa = sW2 + 128 * 68;     // [128]
    const int t = threadIdx.x;
    const int n0 = blockIdx.x * 64;
    const int h = blockIdx.y;

    for (int i = t; i < 64 * 32; i += 256) {
        int n = i >> 5, k4 = (i & 31) * 4;
        *(float4*)&sT[n * 132 + k4] =
            *(const float4*)&g_t[(size_t)(n0 + n) * TCOLS + h * HIDDEN + k4];
    }
    for (int i = t; i < 128 * 16; i += 256) {
        int k = i >> 4, o4 = (i & 15) * 4;
        *(float4*)&sW2[k * 68 + o4] =
            *(const float4*)&W2[(size_t)h * HIDDEN * EDGE_DIM + k * EDGE_DIM + o4];
    }
    if (t < 128) sWa[t] = Wa[h * HIDDEN + t];
    __syncthreads();

    const int ty = t >> 4, tx = t & 15;
    float acc[4][4] = {};
    for (int k = 0; k < HIDDEN; ++k) {
        float4 w = *(const float4*)&sW2[k * 68 + tx * 4];
#pragma unroll
        for (int i = 0; i < 4; ++i) {
            float a = sT[(ty * 4 + i) * 132 + k];
            acc[i][0] += a * w.x; acc[i][1] += a * w.y;
            acc[i][2] += a * w.z; acc[i][3] += a * w.w;
        }
    }
#pragma unroll
    for (int j = 0; j < 4; ++j) {
        int c = h * EDGE_DIM + tx * 4 + j;
        bk_store_pair(c, n0 + ty * 4 + 0, acc[0][j], acc[1][j]);
        bk_store_pair(c, n0 + ty * 4 + 2, acc[2][j], acc[3][j]);
    }
    if (tx == 0) {
        int c = CATDIM + h;
        float q[4];
#pragma unroll
        for (int i = 0; i < 4; ++i) {
            int n = ty * 4 + i;
            float s = 0.f;
            for (int k = 0; k < HIDDEN; ++k) s += sT[n * 132 + k] * sWa[k];
            q[i] = s;
        }
        bk_store_pair(c, n0 + ty * 4 + 0, q[0], q[1]);
        bk_store_pair(c, n0 + ty * 4 + 2, q[2], q[3]);
    }
}

// ---------------- k2: HMMA split-fp16 GEMM (3 passes)  Mu[e, c] = incT @ [P|q] ----------------
// A split hi/lo fp16; B split hi/lo fp16; passes AhBh + AhBl + AlBh.
// CTA 128e x 264c, 256 threads (8 warps: 4m x 2n), warp tile 32e x {136,128}c.
// acc = 2x17x4 = 136 regs -> ~34 independent chains/warp (intra-warp ILP hides latency).
// KCH=64, 2-stage, one sync/chunk; B via single cp.async.bulk; B frags via scalar LDS.
// A stage: 64 k-rows x [hi 256B | lo 256B | pad 16B] = 528B -> 33792B
// B stage: one blocked chunk = 67584B
#define K2_ASZ 33792
#define K2_SS (K2_ASZ + BCHUNK)  /* 101376 */
#define K2_SMEM (2 * K2_SS)      /* 202752 */

__global__ __launch_bounds__(256, 1) void k2_mma(const float* __restrict__ inc,
                                                 const float* __restrict__ ba)
{
    extern __shared__ char sm[];
    __shared__ __align__(8) unsigned long long mbar[2];
    const int t = threadIdx.x;
    const int lane = t & 31, wid = t >> 5;
    const int e0 = blockIdx.x * 128;
    const int wm0 = (wid >> 1) * 32;        // 4 m-groups
    const int nw = wid & 1;                 // 2 n-groups
    const int wn0 = nw ? 136 : 0;
    const int ntcnt = nw ? 16 : 17;
    const uint32_t sb = smem_u32(sm);

    if (t == 0) {
        MBAR_INIT(smem_u32(&mbar[0]), 1);
        MBAR_INIT(smem_u32(&mbar[1]), 1);
    }

    float4 rA[8];
    auto ldgA = [&](int kt) {
#pragma unroll
        for (int it = 0; it < 8; ++it) {
            int idx = t + it * 256;
            int r = idx >> 5, f = idx & 31;
            rA[it] = *(const float4*)&inc[(size_t)(kt * KCH + r) * N_EDGES + e0 + f * 4];
        }
    };
    auto stsA = [&](int s) {
        char* ab = sm + s * K2_SS;
#pragma unroll
        for (int it = 0; it < 8; ++it) {
            int idx = t + it * 256;
            int r = idx >> 5, f = idx & 31;
            float4 v = rA[it];
            __half hx = __float2half_rn(v.x), hy = __float2half_rn(v.y);
            __half hz = __float2half_rn(v.z), hw = __float2half_rn(v.w);
            __half lx = __float2half_rn(v.x - __half2float(hx));
            __half ly = __float2half_rn(v.y - __half2float(hy));
            __half lz = __float2half_rn(v.z - __half2float(hz));
            __half lw = __float2half_rn(v.w - __half2float(hw));
            uint32_t off = r * 528 + f * 8;
            *(__half2*)(ab + off)       = __halves2half2(hx, hy);
            *(__half2*)(ab + off + 4)   = __halves2half2(hz, hw);
            *(__half2*)(ab + off + 256) = __halves2half2(lx, ly);
            *(__half2*)(ab + off + 260) = __halves2half2(lz, lw);
        }
    };
    auto loadB = [&](int s, int kt) {
        if (t == 0) {
            uint32_t mb = smem_u32(&mbar[s]);
            MBAR_EXPECT_TX(mb, (uint32_t)BCHUNK);
            bulk_ld(sb + s * K2_SS + K2_ASZ, g_Bk + (size_t)kt * BCHUNK, BCHUNK, mb);
        }
    };

    float acc[2][17][4];
#pragma unroll
    for (int mt = 0; mt < 2; ++mt)
#pragma unroll
        for (int nt = 0; nt < 17; ++nt)
#pragma unroll
            for (int j = 0; j < 4; ++j) acc[mt][nt][j] = 0.f;

    // prologue: mbar init visible, then stages 0,1 <- chunks 0,1; rA <- chunk 2
    __syncthreads();
    loadB(0, 0);
    loadB(1, 1);
    ldgA(0); stsA(0);
    ldgA(1); stsA(1);
    ldgA(2);
    __syncthreads();

    const int grp = lane >> 3, gi = lane & 7;
    // B lane base: col (wn0 + lane>>2), k-byte (lane&3)*4 within 16B seg entry
    const uint32_t bLane = (wn0 + (lane >> 2)) * 16 + (lane & 3) * 4;
    int ph0 = 0, ph1 = 0;
    for (int kt = 0; kt < NCHUNK; ++kt) {
        const int buf = kt & 1;
        if (buf == 0) { MBAR_WAIT(smem_u32(&mbar[0]), ph0); ph0 ^= 1; }
        else          { MBAR_WAIT(smem_u32(&mbar[1]), ph1); ph1 ^= 1; }

        const uint32_t aBase = sb + buf * K2_SS;
        const uint32_t bBase = aBase + K2_ASZ + bLane;
#pragma unroll
        for (int kk = 0; kk < KCH; kk += 16) {
            uint32_t aH[2][4], aL[2][4];
            const int krow = kk + ((grp & 2) ? 8 : 0) + gi;
#pragma unroll
            for (int mt = 0; mt < 2; ++mt) {
                const uint32_t mcol = wm0 + mt * 16 + ((grp & 1) ? 8 : 0);
                ldmat4t(aH[mt], aBase + krow * 528 + mcol * 2);
                ldmat4t(aL[mt], aBase + krow * 528 + 256 + mcol * 2);
            }
            // seg pair for this kk: hi segs (kk>>3, +1), lo segs (+8, +9)
            const uint32_t bK = bBase + (kk >> 3) * (NB * 16);
#pragma unroll
            for (int nt = 0; nt < 17; ++nt) {
                if (nt < ntcnt) {
                    const uint32_t a0 = bK + nt * 128;        // col += 8 -> +128B
                    uint32_t bh0 = lds32(a0);
                    uint32_t bh1 = lds32(a0 + NB * 16);
                    uint32_t bl0 = lds32(a0 + 8 * (NB * 16));
                    uint32_t bl1 = lds32(a0 + 9 * (NB * 16));
#pragma unroll
                    for (int mt = 0; mt < 2; ++mt) {
                        hmma(acc[mt][nt], aH[mt], bh0, bh1);
                        hmma(acc[mt][nt], aH[mt], bl0, bl1);
                        hmma(acc[mt][nt], aL[mt], bh0, bh1);
                    }
                }
            }
        }
        __syncthreads();   // all reads of stage buf done; safe to refill
        if (kt + 2 < NCHUNK) {
            loadB(buf, kt + 2);
            stsA(buf);
            if (kt + 3 < NCHUNK) ldgA(kt + 3);
        }
    }

    // epilogue
#pragma unroll
    for (int mt = 0; mt < 2; ++mt) {
        const int e = e0 + wm0 + mt * 16 + (lane >> 2);
#pragma unroll
        for (int nt = 0; nt < 17; ++nt) {
            if (nt < ntcnt) {
                const int c = wn0 + nt * 8 + (lane & 3) * 2;
                if (c < CATDIM) {
                    *(float2*)&g_Mu[(size_t)e * CATDIM + c] =
                        make_float2(acc[mt][nt][0], acc[mt][nt][1]);
                    *(float2*)&g_Mu[(size_t)(e + 8) * CATDIM + c] =
                        make_float2(acc[mt][nt][2], acc[mt][nt][3]);
                } else if (c < CATDIM + HEADS) {
                    const int h0 = c - CATDIM;
                    float b0 = ba[h0], b1 = ba[h0 + 1];
                    float s0 = acc[mt][nt][0] + b0, s1 = acc[mt][nt][1] + b1;
                    float s2 = acc[mt][nt][2] + b0, s3 = acc[mt][nt][3] + b1;
                    s0 = s0 > 0.f ? s0 : 0.2f * s0;
                    s1 = s1 > 0.f ? s1 : 0.2f * s1;
                    s2 = s2 > 0.f ? s2 : 0.2f * s2;
                    s3 = s3 > 0.f ? s3 : 0.2f * s3;
                    g_score[h0 * N_EDGES + e] = s0;
                    g_score[(h0 + 1) * N_EDGES + e] = s1;
                    g_score[h0 * N_EDGES + e + 8] = s2;
                    g_score[(h0 + 1) * N_EDGES + e + 8] = s3;
                }
            }
        }
    }
}

// ---------------- k4: softmax over edges, per head ----------------
__global__ void k4_softmax()
{
    __shared__ float red[1024];
    const int h = blockIdx.x;
    const int t = threadIdx.x;
    const float* srow = &g_score[h * N_EDGES];

    float m = -3.4e38f;
    for (int i = t; i < N_EDGES; i += 1024) m = fmaxf(m, srow[i]);
    red[t] = m;
    __syncthreads();
    for (int s = 512; s > 0; s >>= 1) {
        if (t < s) red[t] = fmaxf(red[t], red[t + s]);
        __syncthreads();
    }
    m = red[0];
    __syncthreads();

    float sum = 0.f;
    for (int i = t; i < N_EDGES; i += 1024) sum += expf(srow[i] - m);
    red[t] = sum;
    __syncthreads();
    for (int s = 512; s > 0; s >>= 1) {
        if (t < s) red[t] += red[t + s];
        __syncthreads();
    }
    float inv = 1.0f / red[0];

    for (int i = t; i < N_EDGES; i += 1024)
        g_coeff[h * N_EDGES + i] = expf(srow[i] - m) * inv;
}

// ---------------- k5: u = coeff*Mu + b2 ; column min/max ----------------
__global__ __launch_bounds__(256) void k5_u(const float* __restrict__ b2)
{
    const int c = threadIdx.x;
    const int e0 = blockIdx.x * 64;
    const int h = c >> 6;
    const float bb = b2[c];
    float mn = 3.4e38f, mx = -3.4e38f;
    for (int i = 0; i < 64; ++i) {
        int e = e0 + i;
        float u = g_coeff[h * N_EDGES + e] * g_Mu[(size_t)e * CATDIM + c] + bb;
        g_U[(size_t)e * CATDIM + c] = u;
        mn = fminf(mn, u); mx = fmaxf(mx, u);
    }
    atomicMin(&g_mn_bits[c], f2ord(mn));
    atomicMax(&g_mx_bits[c], f2ord(mx));
}

// ---------------- k6: out = relu(minmax_norm(U)) @ Wout + bout ----------------
__global__ __launch_bounds__(256) void k6_out(const float* __restrict__ Wout,
                                              const float* __restrict__ bout,
                                              float* __restrict__ out)
{
    __shared__ float sX[32 * CATDIM];
    __shared__ float sMin[CATDIM];
    __shared__ float sInv[CATDIM];
    const int t = threadIdx.x;
    const int e0 = blockIdx.x * 32;

    for (int i = t; i < CATDIM; i += 256) {
        float mn = ord2f(g_mn_bits[i]);
        float mx = ord2f(g_mx_bits[i]);
        sMin[i] = mn;
        sInv[i] = 1.0f / (mx - mn + 1e-8f);
    }
    __syncthreads();
    for (int i = t; i < 32 * CATDIM / 4; i += 256) {
        int l = i * 4; int e = l >> 8; int c = l & 255;
        float4 v = *(const float4*)&g_U[(size_t)(e0 + e) * CATDIM + c];
        v.x = fmaxf((v.x - sMin[c + 0]) * sInv[c + 0], 0.f);
        v.y = fmaxf((v.y - sMin[c + 1]) * sInv[c + 1], 0.f);
        v.z = fmaxf((v.z - sMin[c + 2]) * sInv[c + 2], 0.f);
        v.w = fmaxf((v.w - sMin[c + 3]) * sInv[c + 3], 0.f);
        *(float4*)&sX[l] = v;
    }
    __syncthreads();

    const int ty = t >> 4, tx = t & 15;
    float acc[2][4] = {{0.f,0.f,0.f,0.f},{0.f,0.f,0.f,0.f}};
#pragma unroll 4
    for (int c = 0; c < CATDIM; ++c) {
        float4 w = *(const float4*)&Wout[c * OUT_DIM + tx * 4];
#pragma unroll
        for (int ee = 0; ee < 2; ++ee) {
            float xv = sX[(ty + ee * 16) * CATDIM + c];
            acc[ee][0] += xv * w.x; acc[ee][1] += xv * w.y;
            acc[ee][2] += xv * w.z; acc[ee][3] += xv * w.w;
        }
    }
    float4 bo = *(const float4*)&bout[tx * 4];
#pragma unroll
    for (int ee = 0; ee < 2; ++ee) {
        int e = e0 + ty + ee * 16;
        out[(size_t)e * OUT_DIM + tx * 4 + 0] = acc[ee][0] + bo.x;
        out[(size_t)e * OUT_DIM + tx * 4 + 1] = acc[ee][1] + bo.y;
        out[(size_t)e * OUT_DIM + tx * 4 + 2] = acc[ee][2] + bo.z;
        out[(size_t)e * OUT_DIM + tx * 4 + 3] = acc[ee][3] + bo.w;
    }
}

// ---------------- launch ----------------
extern "C" void kernel_launch(void* const* d_in, const int* in_sizes, int n_in,
                              void* d_out, int out_size)
{
    (void)in_sizes; (void)n_in; (void)out_size;
    const float* node = (const float*)d_in[0];
    const float* inc  = (const float*)d_in[1];
    const float* W1   = (const float*)d_in[2];
    const float* b1   = (const float*)d_in[3];
    const float* Wa   = (const float*)d_in[4];
    const float* ba   = (const float*)d_in[5];
    const float* W2   = (const float*)d_in[6];
    const float* b2   = (const float*)d_in[7];
    const float* Wout = (const float*)d_in[8];
    const float* bout = (const float*)d_in[9];
    float* out = (float*)d_out;

    cudaFuncSetAttribute(k2_mma, cudaFuncAttributeMaxDynamicSharedMemorySize, K2_SMEM);
    cudaFuncSetAttribute(k1b_project, cudaFuncAttributeMaxDynamicSharedMemorySize, 69120);

    k0_init<<<64, 256>>>();
    k1_node_transform<<<dim3(N_NODES / 64, TCOLS / 64), 256>>>(node, W1, b1);
    k1b_project<<<dim3(N_NODES / 64, HEADS), 256, 69120>>>(W2, Wa);
    k2_mma<<<N_EDGES / 128, 256, K2_SMEM>>>(inc, ba);
    k4_softmax<<<HEADS, 1024>>>();
    k5_u<<<N_EDGES / 64, 256>>>(b2);
    k6_out<<<N_EDGES / 32, 256>>>(Wout, bout, out);
}